// round 13
// baseline (speedup 1.0000x reference)
#include <cuda_runtime.h>
#include <cuda_bf16.h>
#include <cstdint>

#define BB 4
#define SS 2048
#define DD 1024
#define DHE 64
#define SCALE 0.125f

// ---------------- scratch (device globals) ----------------
static __device__ float g_P[6][BB * SS * DHE];  // only [5]=Vc used in f32
static __device__ __nv_bfloat16 g_Ph[5][BB * SS * DHE];  // hi of Qu,Ku,Vu,Qc,Kc
static __device__ __nv_bfloat16 g_Pl[5][BB * SS * DHE];  // lo
static __device__ __nv_bfloat16 g_Vth[(size_t)BB * DHE * SS];  // Vc^T [b][d][s]
static __device__ __nv_bfloat16 g_Vtl[(size_t)BB * DHE * SS];
static __device__ __nv_bfloat16 g_xh[(size_t)BB * SS * DD];
static __device__ __nv_bfloat16 g_xl[(size_t)BB * SS * DD];
static __device__ __nv_bfloat16 g_wh[6][DHE * DD];  // [head][n][k]
static __device__ __nv_bfloat16 g_wl[6][DHE * DD];
static __device__ __nv_bfloat16 g_t1h[(size_t)BB * SS * SS];
static __device__ __nv_bfloat16 g_t1l[(size_t)BB * SS * SS];
static __device__ __nv_bfloat16 g_sgh[(size_t)BB * SS * SS];
static __device__ __nv_bfloat16 g_sgl[(size_t)BB * SS * SS];
static __device__ float g_suA[(size_t)BB * SS * SS];
static __device__ float g_suB[(size_t)BB * SS * SS];
// split-KV partials: 8 chunks (2 k-tiles of 128 each), 16 i-tiles of 128 rows
static __device__ float g_am[BB][8][16][128];
static __device__ float g_al[BB][8][16][128];
static __device__ float g_aO[BB][8][16][128 * 64];

// ---------------- helpers (compute_103-safe) ----------------
__device__ __forceinline__ uint32_t smem_to_u32(const void* p) {
    uint32_t a;
    asm("{ .reg .u64 t; cvta.to.shared.u64 t, %1; cvt.u32.u64 %0, t; }" : "=r"(a) : "l"(p));
    return a;
}
#define SW128(o) ((o) ^ (((o) >> 3) & 0x70))

__device__ __forceinline__ void ldsm4(uint32_t* r, uint32_t addr) {
    asm volatile("ldmatrix.sync.aligned.m8n8.x4.shared.b16 {%0,%1,%2,%3}, [%4];"
        : "=r"(r[0]), "=r"(r[1]), "=r"(r[2]), "=r"(r[3]) : "r"(addr));
}
__device__ __forceinline__ void mma16816(float* c, const uint32_t* a,
                                         uint32_t b0, uint32_t b1) {
    asm volatile("mma.sync.aligned.m16n8k16.row.col.f32.bf16.bf16.f32 "
        "{%0,%1,%2,%3}, {%4,%5,%6,%7}, {%8,%9}, {%0,%1,%2,%3};"
        : "+f"(c[0]), "+f"(c[1]), "+f"(c[2]), "+f"(c[3])
        : "r"(a[0]), "r"(a[1]), "r"(a[2]), "r"(a[3]), "r"(b0), "r"(b1));
}

__device__ __forceinline__ float fast_rcp(float y) {
    float r = __int_as_float(0x7EF127EAu - __float_as_int(y));
    r = r * fmaf(-y, r, 2.0f);
    r = r * fmaf(-y, r, 2.0f);
    r = r * fmaf(-y, r, 2.0f);
    return r;
}
__device__ __forceinline__ float fast_sigmoid(float x) {
    const float t = __expf(-fmaxf(x, -80.f));
    return fast_rcp(1.f + t);
}
__device__ __forceinline__ float fast_silu(float x) {
    return x * fast_sigmoid(x);
}
__device__ __forceinline__ void split2(float v0, float v1, uint32_t& h, uint32_t& l) {
    const __nv_bfloat16 h0 = __float2bfloat16(v0), h1 = __float2bfloat16(v1);
    const __nv_bfloat16 l0 = __float2bfloat16(v0 - __bfloat162float(h0));
    const __nv_bfloat16 l1 = __float2bfloat16(v1 - __bfloat162float(h1));
    union { __nv_bfloat162 b; uint32_t u; } H, L;
    H.b = __halves2bfloat162(h0, h1);
    L.b = __halves2bfloat162(l0, l1);
    h = H.u; l = L.u;
}

// ---------------------------------------------------------------------------
// K0: convert x AND weights -> bf16 hi/lo (merged, one launch)
// ---------------------------------------------------------------------------
__global__ void k_cvt(const float* __restrict__ x,
                      const float* __restrict__ w0, const float* __restrict__ w1,
                      const float* __restrict__ w2, const float* __restrict__ w3,
                      const float* __restrict__ w4, const float* __restrict__ w5) {
    const size_t n_x = (size_t)BB * SS * DD;
    const size_t n_w = 6 * DD * DHE;
    const size_t n = n_x + n_w;
    for (size_t i = (size_t)blockIdx.x * blockDim.x + threadIdx.x; i < n;
         i += (size_t)gridDim.x * blockDim.x) {
        if (i < n_x) {
            const float v = x[i];
            const __nv_bfloat16 h = __float2bfloat16(v);
            g_xh[i] = h;
            g_xl[i] = __float2bfloat16(v - __bfloat162float(h));
        } else {
            const int j = (int)(i - n_x);
            const int head = j >> 16;
            const int rem = j & 65535;
            const int k = rem >> 6, nn = rem & 63;
            const float* w = head == 0 ? w0 : head == 1 ? w1 : head == 2 ? w2
                           : head == 3 ? w3 : head == 4 ? w4 : w5;
            const float v = w[k * DHE + nn];
            const __nv_bfloat16 h = __float2bfloat16(v);
            g_wh[head][nn * DD + k] = h;
            g_wl[head][nn * DD + k] = __float2bfloat16(v - __bfloat162float(h));
        }
    }
}

// ---------------------------------------------------------------------------
// K1: projections via mma.sync bf16 hi/lo.  out[h] = x @ w[h].
// ---------------------------------------------------------------------------
__global__ void __launch_bounds__(256) k_proj_mma() {
    extern __shared__ char smem[];
    const uint32_t tiles = (smem_to_u32(smem) + 1023u) & ~1023u;
    const int row0 = blockIdx.x * 128, head = blockIdx.y;

    const int tid = threadIdx.x;
    const int wid = tid >> 5, lane = tid & 31;
    const int wm = wid & 3, wn = wid >> 2;
    const int lrow = lane & 15;
    const uint32_t kbl = (lane >> 4) * 16;

#define PJ_LOAD(stage, ch) do { \
    const uint32_t _st = tiles + (stage) * 49152; \
    _Pragma("unroll") \
    for (int q = 0; q < 4; q++) { \
        const int r = (tid >> 3) + q * 32; \
        const int c16 = tid & 7; \
        const uint32_t so = SW128((uint32_t)(r * 128 + c16 * 16)); \
        const size_t go = (size_t)(row0 + r) * DD + (ch) + c16 * 8; \
        asm volatile("cp.async.cg.shared.global [%0], [%1], 16;" :: "r"(_st + so), "l"(g_xh + go)); \
        asm volatile("cp.async.cg.shared.global [%0], [%1], 16;" :: "r"(_st + 16384 + so), "l"(g_xl + go)); \
    } \
    _Pragma("unroll") \
    for (int q = 0; q < 2; q++) { \
        const int r = (tid >> 3) + q * 32; \
        const int c16 = tid & 7; \
        const uint32_t so = SW128((uint32_t)(r * 128 + c16 * 16)); \
        const size_t go = (size_t)r * DD + (ch) + c16 * 8; \
        asm volatile("cp.async.cg.shared.global [%0], [%1], 16;" :: "r"(_st + 32768 + so), "l"(g_wh[head] + go)); \
        asm volatile("cp.async.cg.shared.global [%0], [%1], 16;" :: "r"(_st + 40960 + so), "l"(g_wl[head] + go)); \
    } \
    asm volatile("cp.async.commit_group;"); \
} while (0)

    float acc[2][4][4];
#pragma unroll
    for (int mf = 0; mf < 2; mf++)
#pragma unroll
        for (int nf = 0; nf < 4; nf++)
#pragma unroll
            for (int q = 0; q < 4; q++) acc[mf][nf][q] = 0.f;

    PJ_LOAD(0, 0);

    for (int c = 0; c < DD / 64; c++) {
        const int s = c & 1;
        if (c + 1 < DD / 64) {
            PJ_LOAD(s ^ 1, (c + 1) * 64);
            asm volatile("cp.async.wait_group 1;");
        } else {
            asm volatile("cp.async.wait_group 0;");
        }
        __syncthreads();

        const uint32_t stAh = tiles + s * 49152;
        const uint32_t stAl = stAh + 16384;
        const uint32_t stBh = stAh + 32768;
        const uint32_t stBl = stAh + 40960;

#pragma unroll
        for (int ks = 0; ks < 4; ks++) {
            const uint32_t kb = ks * 32 + kbl;
            uint32_t ah[2][4], al[2][4], bh[2][4], bl[2][4];
#pragma unroll
            for (int mf = 0; mf < 2; mf++) {
                const uint32_t off = SW128((uint32_t)((wm * 32 + mf * 16 + lrow) * 128) + kb);
                ldsm4(ah[mf], stAh + off);
                ldsm4(al[mf], stAl + off);
            }
#pragma unroll
            for (int np = 0; np < 2; np++) {
                const uint32_t off = SW128((uint32_t)((wn * 32 + np * 16 + lrow) * 128) + kb);
                ldsm4(bh[np], stBh + off);
                ldsm4(bl[np], stBl + off);
            }
#pragma unroll
            for (int mf = 0; mf < 2; mf++)
#pragma unroll
                for (int nf = 0; nf < 4; nf++) {
                    const int np = nf >> 1, sel = nf & 1;
                    mma16816(acc[mf][nf], ah[mf], bh[np][sel], bh[np][sel + 2]);
                    mma16816(acc[mf][nf], ah[mf], bl[np][sel], bl[np][sel + 2]);
                    mma16816(acc[mf][nf], al[mf], bh[np][sel], bh[np][sel + 2]);
                }
        }
        __syncthreads();
    }
#undef PJ_LOAD

    const int rr = lane >> 2, cc = (lane & 3) * 2;
    if (head == 5) {
        float* C = g_P[5];
#pragma unroll
        for (int mf = 0; mf < 2; mf++) {
            const int gr = row0 + wm * 32 + mf * 16 + rr;
#pragma unroll
            for (int nf = 0; nf < 4; nf++) {
                const int gc = wn * 32 + nf * 8 + cc;
                *(float2*)(C + (size_t)gr * DHE + gc) = make_float2(acc[mf][nf][0], acc[mf][nf][1]);
                *(float2*)(C + (size_t)(gr + 8) * DHE + gc) = make_float2(acc[mf][nf][2], acc[mf][nf][3]);
            }
        }
    } else {
        __nv_bfloat16* Hh = g_Ph[head];
        __nv_bfloat16* Hl = g_Pl[head];
#pragma unroll
        for (int mf = 0; mf < 2; mf++) {
            const int gr = row0 + wm * 32 + mf * 16 + rr;
#pragma unroll
            for (int nf = 0; nf < 4; nf++) {
                const int gc = wn * 32 + nf * 8 + cc;
                uint32_t h0, l0, h1, l1;
                split2(acc[mf][nf][0], acc[mf][nf][1], h0, l0);
                split2(acc[mf][nf][2], acc[mf][nf][3], h1, l1);
                *(uint32_t*)(Hh + (size_t)gr * DHE + gc) = h0;
                *(uint32_t*)(Hl + (size_t)gr * DHE + gc) = l0;
                *(uint32_t*)(Hh + (size_t)(gr + 8) * DHE + gc) = h1;
                *(uint32_t*)(Hl + (size_t)(gr + 8) * DHE + gc) = l1;
            }
        }
    }
}

// ---------------------------------------------------------------------------
// K1b: transpose Vc -> [b][d][s] bf16 hi/lo.  grid (64 s-tiles of 32, 4 b).
// ---------------------------------------------------------------------------
__global__ void k_vt() {
    __shared__ float ts[32][65];
    const int s0 = blockIdx.x * 32, b = blockIdx.y;
    const int tid = threadIdx.x;
    for (int t = tid; t < 2048; t += 256) {
        const int r = t >> 6, c = t & 63;
        ts[r][c] = g_P[5][((size_t)b * SS + s0 + r) * DHE + c];
    }
    __syncthreads();
    for (int t = tid; t < 2048; t += 256) {
        const int d = t >> 5, sc = t & 31;
        const float v = ts[sc][d];
        const __nv_bfloat16 h = __float2bfloat16(v);
        const size_t o = ((size_t)b * DHE + d) * SS + s0 + sc;
        g_Vth[o] = h;
        g_Vtl[o] = __float2bfloat16(v - __bfloat162float(h));
    }
}

// ---------------------------------------------------------------------------
// K2: term1 / sigmoid gate via mma.sync, 128x128 tiles.
// grid (136 tri-pairs, 4 b, 2 modes), 256 thr, 66560 B smem.
// ---------------------------------------------------------------------------
__global__ void __launch_bounds__(256) k_pair_mma() {
    extern __shared__ char smem[];
    const uint32_t tiles = (smem_to_u32(smem) + 1023u) & ~1023u;

    const int mode = blockIdx.z, b = blockIdx.y;
    int pp = blockIdx.x;
    int d = 15;
    while (pp >= 16 - d) { pp -= 16 - d; d--; }
    const int rt = (mode == 0) ? (pp + d) : pp;
    const int ct = (mode == 0) ? pp : (pp + d);
    const int i0 = rt * 128, j0 = ct * 128;
    const int hA = (mode == 0) ? 3 : 0;
    const int hB = (mode == 0) ? 2 : 1;

    const int tid = threadIdx.x;
    const int wid = tid >> 5, lane = tid & 31;

    {
        const int ltile = tid >> 6;
        const int llane = tid & 63;
        const int rl = llane >> 3, c16 = llane & 7;
        const __nv_bfloat16* src =
            (ltile == 0) ? g_Ph[hA] + ((size_t)b * SS + i0) * DHE :
            (ltile == 1) ? g_Pl[hA] + ((size_t)b * SS + i0) * DHE :
            (ltile == 2) ? g_Ph[hB] + ((size_t)b * SS + j0) * DHE :
                           g_Pl[hB] + ((size_t)b * SS + j0) * DHE;
        const __nv_bfloat16* g = src + (size_t)rl * DHE + c16 * 8;
        const uint32_t tsm = tiles + ltile * 16384;
#pragma unroll
        for (int q = 0; q < 16; q++) {
            const uint32_t so = SW128((uint32_t)((q * 8 + rl) * 128 + c16 * 16));
            asm volatile("cp.async.cg.shared.global [%0], [%1], 16;"
                :: "r"(tsm + so), "l"(g + (size_t)q * 8 * DHE));
        }
        asm volatile("cp.async.commit_group;");
        asm volatile("cp.async.wait_group 0;");
    }
    __syncthreads();

    float acc[2][8][4];
#pragma unroll
    for (int mf = 0; mf < 2; mf++)
#pragma unroll
        for (int nf = 0; nf < 8; nf++)
#pragma unroll
            for (int q = 0; q < 4; q++) acc[mf][nf][q] = 0.f;

    const int wm = wid >> 1, wn = wid & 1;
    const int lrow = lane & 15;
    const uint32_t kbl = (lane >> 4) * 16;
    const uint32_t stAh = tiles, stAl = tiles + 16384;
    const uint32_t stBh = tiles + 32768, stBl = tiles + 49152;

#pragma unroll
    for (int ks = 0; ks < 4; ks++) {
        const uint32_t kb = ks * 32 + kbl;
        uint32_t ah[2][4], al[2][4], bh[4][4], bl[4][4];
#pragma unroll
        for (int mf = 0; mf < 2; mf++) {
            const uint32_t off = SW128((uint32_t)((wm * 32 + mf * 16 + lrow) * 128) + kb);
            ldsm4(ah[mf], stAh + off);
            ldsm4(al[mf], stAl + off);
        }
#pragma unroll
        for (int np = 0; np < 4; np++) {
            const uint32_t off = SW128((uint32_t)((wn * 64 + np * 16 + lrow) * 128) + kb);
            ldsm4(bh[np], stBh + off);
            ldsm4(bl[np], stBl + off);
        }
#pragma unroll
        for (int mf = 0; mf < 2; mf++)
#pragma unroll
            for (int nf = 0; nf < 8; nf++) {
                const int np = nf >> 1, sel = nf & 1;
                mma16816(acc[mf][nf], ah[mf], bh[np][sel], bh[np][sel + 2]);
                mma16816(acc[mf][nf], ah[mf], bl[np][sel], bl[np][sel + 2]);
                mma16816(acc[mf][nf], al[mf], bh[np][sel], bh[np][sel + 2]);
            }
    }

    const size_t boff = (size_t)b * SS * SS;
    __nv_bfloat16* outh = (mode == 0 ? g_t1h : g_sgh) + boff;
    __nv_bfloat16* outl = (mode == 0 ? g_t1l : g_sgl) + boff;
    const int rr = lane >> 2, cc = (lane & 3) * 2;
#pragma unroll
    for (int mf = 0; mf < 2; mf++) {
#pragma unroll
        for (int half = 0; half < 2; half++) {
            const int gi = i0 + wm * 32 + mf * 16 + half * 8 + rr;
#pragma unroll
            for (int nf = 0; nf < 8; nf++) {
                const int gc = j0 + wn * 64 + nf * 8 + cc;
                float v0 = acc[mf][nf][half * 2 + 0] * SCALE;
                float v1 = acc[mf][nf][half * 2 + 1] * SCALE;
                if (mode == 0) {
                    v0 = (gc <= gi) ? v0 : 0.f;
                    v1 = (gc + 1 <= gi) ? v1 : 0.f;
                } else {
                    v0 = (gc > gi) ? fast_sigmoid(v0) : 0.f;
                    v1 = (gc + 1 > gi) ? fast_sigmoid(v1) : 0.f;
                }
                uint32_t h, l;
                split2(v0, v1, h, l);
                *(uint32_t*)(outh + (size_t)gi * SS + gc) = h;
                *(uint32_t*)(outl + (size_t)gi * SS + gc) = l;
            }
        }
    }
}

// ---------------------------------------------------------------------------
// K3: S_u via mma.sync bf16x2-split, j-SPLIT, 256 thr, 3-STAGE cp.async
// pipeline with ONE __syncthreads per chunk (stage reuse distance = 2).
// grid (272 = 136 pairs * 2 segs, 1, 4 b), 256 thr, 197632 B smem.
// ---------------------------------------------------------------------------
__global__ void __launch_bounds__(256) k_su_mma() {
    extern __shared__ char smem[];
    const uint32_t tiles = (smem_to_u32(smem) + 1023u) & ~1023u;

    const int b = blockIdx.z;
    const int seg = blockIdx.x & 1;
    int pp = blockIdx.x >> 1;
    int d = 15;
    while (pp >= 16 - d) { pp -= 16 - d; d--; }
    const int kt = pp, it = pp + d;
    const int i0 = it * 128, k0 = kt * 128;

    int jbeg = k0, jend = (it + 1) * 128;
    const int mid = jbeg + ((jend - jbeg) >> 1);
    if (seg == 0) jend = mid; else jbeg = mid;
    const int nch = (jend - jbeg) >> 6;

    const int tid = threadIdx.x;
    const int wid = tid >> 5, lane = tid & 31;

    const int ltile = tid >> 6;
    const int llane = tid & 63;
    const int rl = llane >> 3;
    const int c16 = llane & 7;
    const size_t boff = (size_t)b * SS * SS;
    const __nv_bfloat16* src =
        (ltile == 0) ? g_t1h + boff + (size_t)i0 * SS :
        (ltile == 1) ? g_t1l + boff + (size_t)i0 * SS :
        (ltile == 2) ? g_sgh + boff + (size_t)k0 * SS :
                       g_sgl + boff + (size_t)k0 * SS;
    const __nv_bfloat16* gbase = src + (size_t)rl * SS + c16 * 8;
    const uint32_t tsm = tiles + ltile * 16384;

#define SU_LOAD_CHUNK(stage, j0v) do { \
    const __nv_bfloat16* _g = gbase + (j0v); \
    const uint32_t _base = tsm + (uint32_t)(stage) * 65536u; \
    _Pragma("unroll") \
    for (int q = 0; q < 16; q++) { \
        uint32_t so = (uint32_t)((q * 8 + rl) * 128 + c16 * 16); \
        uint32_t sa = _base + SW128(so); \
        asm volatile("cp.async.cg.shared.global [%0], [%1], 16;" :: "r"(sa), "l"(_g + (size_t)q * 8 * SS)); \
    } \
    asm volatile("cp.async.commit_group;"); \
} while (0)

    float acc[2][8][4];
#pragma unroll
    for (int mf = 0; mf < 2; mf++)
#pragma unroll
        for (int nf = 0; nf < 8; nf++)
#pragma unroll
            for (int q = 0; q < 4; q++) acc[mf][nf][q] = 0.f;

    const int wm = wid >> 1, wn = wid & 1;
    const int lrow = lane & 15;
    const uint32_t kbl = (lane >> 4) * 16;

    SU_LOAD_CHUNK(0, jbeg);
    if (1 < nch) SU_LOAD_CHUNK(1, jbeg + 64);

    int s = 0;
    for (int i = 0; i < nch; i++) {
        if (i + 1 < nch) {
            asm volatile("cp.async.wait_group 1;");
        } else {
            asm volatile("cp.async.wait_group 0;");
        }
        __syncthreads();  // chunk i visible; all warps past compute of i-1

        if (i + 2 < nch) {
            int s2 = s + 2; if (s2 >= 3) s2 -= 3;
            SU_LOAD_CHUNK(s2, jbeg + (i + 2) * 64);
        }

        const uint32_t stAh = tiles + (uint32_t)s * 65536u;
        const uint32_t stAl = stAh + 16384;
        const uint32_t stBh = stAh + 32768;
        const uint32_t stBl = stAh + 49152;

#pragma unroll
        for (int ks = 0; ks < 4; ks++) {
            const uint32_t kb = ks * 32 + kbl;
            uint32_t ah[2][4], al[2][4], bh[4][4], bl[4][4];
#pragma unroll
            for (int mf = 0; mf < 2; mf++) {
                const uint32_t off = SW128((uint32_t)((wm * 32 + mf * 16 + lrow) * 128) + kb);
                ldsm4(ah[mf], stAh + off);
                ldsm4(al[mf], stAl + off);
            }
#pragma unroll
            for (int np = 0; np < 4; np++) {
                const uint32_t off = SW128((uint32_t)((wn * 64 + np * 16 + lrow) * 128) + kb);
                ldsm4(bh[np], stBh + off);
                ldsm4(bl[np], stBl + off);
            }
#pragma unroll
            for (int mf = 0; mf < 2; mf++)
#pragma unroll
                for (int nf = 0; nf < 8; nf++) {
                    const int np = nf >> 1, sel = nf & 1;
                    mma16816(acc[mf][nf], ah[mf], bh[np][sel], bh[np][sel + 2]);
                    mma16816(acc[mf][nf], ah[mf], bl[np][sel], bl[np][sel + 2]);
                    mma16816(acc[mf][nf], al[mf], bh[np][sel], bh[np][sel + 2]);
                }
        }
        if (++s >= 3) s = 0;
    }
#undef SU_LOAD_CHUNK

    float* C = (seg ? g_suB : g_suA) + boff;
    const int rr = lane >> 2, cc = (lane & 3) * 2;
#pragma unroll
    for (int mf = 0; mf < 2; mf++) {
        const int gr = i0 + wm * 32 + mf * 16 + rr;
#pragma unroll
        for (int nf = 0; nf < 8; nf++) {
            const int gc = k0 + wn * 64 + nf * 8 + cc;
            *(float2*)(C + (size_t)gr * SS + gc) = make_float2(acc[mf][nf][0], acc[mf][nf][1]);
            *(float2*)(C + (size_t)(gr + 8) * SS + gc) = make_float2(acc[mf][nf][2], acc[mf][nf][3]);
        }
    }
}

// ---------------------------------------------------------------------------
// K4: flash attention partial via mma.sync (2 k-tiles per chunk).
// grid (16 it, 8 chunk, 4 b), 256 thr, 99328 B smem.
// ---------------------------------------------------------------------------
__global__ void __launch_bounds__(256) k_attn_mma() {
    const int it = blockIdx.x, chunk = blockIdx.y, b = blockIdx.z;
    if (chunk * 2 > it) return;
    const int kt_beg = chunk * 2;
    const int kt_end = min(kt_beg + 2, it + 1);
    const int i0 = it * 128;

    extern __shared__ char smem[];
    const uint32_t sb = (smem_to_u32(smem) + 1023u) & ~1023u;
    const uint32_t smQ = sb;
    const uint32_t smK = sb + 32768;
    const uint32_t smV = sb + 65536;

    const int tid = threadIdx.x;
    const int wid = tid >> 5, lane = tid & 31;
    const int m0 = wid * 16;
    const int lrow = lane & 15;
    const uint32_t kbl = (lane >> 4) * 16;
    const int rr = lane >> 2, cc = (lane & 3) * 2;

    for (int t = tid; t < 2048; t += 256) {
        const int half = t >> 10, r = (t >> 3) & 127, c16 = t & 7;
        const __nv_bfloat16* src = (half ? g_Pl[3] : g_Ph[3])
            + ((size_t)b * SS + i0 + r) * DHE + c16 * 8;
        const uint32_t dst = smQ + half * 16384 + SW128((uint32_t)(r * 128 + c16 * 16));
        asm volatile("cp.async.cg.shared.global [%0], [%1], 16;" :: "r"(dst), "l"(src));
    }
    asm volatile("cp.async.commit_group;");

    const float* SuA = g_suA + (size_t)b * SS * SS;
    const float* SuB = g_suB + (size_t)b * SS * SS;

    float m[2] = {-1e30f, -1e30f}, l[2] = {0.f, 0.f};
    float accO[8][4];
#pragma unroll
    for (int nf = 0; nf < 8; nf++)
#pragma unroll
        for (int q = 0; q < 4; q++) accO[nf][q] = 0.f;

    for (int kt = kt_beg; kt < kt_end; kt++) {
        const int k0t = kt * 128;
        __syncthreads();
        for (int t = tid; t < 2048; t += 256) {
            const int half = t >> 10, r = (t >> 3) & 127, c16 = t & 7;
            const __nv_bfloat16* src = (half ? g_Pl[4] : g_Ph[4])
                + ((size_t)b * SS + k0t + r) * DHE + c16 * 8;
            const uint32_t dst = smK + half * 16384 + SW128((uint32_t)(r * 128 + c16 * 16));
            asm volatile("cp.async.cg.shared.global [%0], [%1], 16;" :: "r"(dst), "l"(src));
        }
        for (int t = tid; t < 2048; t += 256) {
            const int half = t >> 10, rw = (t >> 3) & 127, c16 = t & 7;
            const int dd = rw & 63, sub = rw >> 6;
            const __nv_bfloat16* src = (half ? g_Vtl : g_Vth)
                + ((size_t)b * DHE + dd) * SS + k0t + sub * 64 + c16 * 8;
            const uint32_t dst = smV + half * 16384 + sub * 8192
                + SW128((uint32_t)(dd * 128 + c16 * 16));
            asm volatile("cp.async.cg.shared.global [%0], [%1], 16;" :: "r"(dst), "l"(src));
        }
        asm volatile("cp.async.commit_group;");
        asm volatile("cp.async.wait_group 0;");
        __syncthreads();

        float accS[16][4];
#pragma unroll
        for (int nf = 0; nf < 16; nf++)
#pragma unroll
            for (int q = 0; q < 4; q++) accS[nf][q] = 0.f;

#pragma unroll
        for (int ks = 0; ks < 4; ks++) {
            const uint32_t kb = ks * 32 + kbl;
            uint32_t ah[4], al[4];
            const uint32_t aoff = SW128((uint32_t)((m0 + lrow) * 128) + kb);
            ldsm4(ah, smQ + aoff);
            ldsm4(al, smQ + 16384 + aoff);
#pragma unroll
            for (int np = 0; np < 8; np++) {
                uint32_t bh[4], bl[4];
                const uint32_t boffs = SW128((uint32_t)((np * 16 + lrow) * 128) + kb);
                ldsm4(bh, smK + boffs);
                ldsm4(bl, smK + 16384 + boffs);
#pragma unroll
                for (int sel = 0; sel < 2; sel++) {
                    const int nf = np * 2 + sel;
                    mma16816(accS[nf], ah, bh[sel], bh[sel + 2]);
                    mma16816(accS[nf], ah, bl[sel], bl[sel + 2]);
                    mma16816(accS[nf], al, bh[sel], bh[sel + 2]);
                }
            }
        }

        const bool diag = (kt == it);
#pragma unroll
        for (int nf = 0; nf < 16; nf++) {
            const int gk = k0t + nf * 8 + cc;
#pragma unroll
            for (int half = 0; half < 2; half++) {
                const int gi = i0 + m0 + half * 8 + rr;
                const float2 a2 = *(const float2*)(SuA + (size_t)gi * SS + gk);
                const float2 b2 = *(const float2*)(SuB + (size_t)gi * SS + gk);
                float v0 = accS[nf][half * 2 + 0] * SCALE - fast_silu(a2.x + b2.x);
                float v1 = accS[nf][half * 2 + 1] * SCALE - fast_silu(a2.y + b2.y);
                if (diag) {
                    if (gk > gi) v0 = -1e30f;
                    if (gk + 1 > gi) v1 = -1e30f;
                }
                accS[nf][half * 2 + 0] = v0;
                accS[nf][half * 2 + 1] = v1;
            }
        }

#pragma unroll
        for (int half = 0; half < 2; half++) {
            float mx = -1e30f;
#pragma unroll
            for (int nf = 0; nf < 16; nf++)
                mx = fmaxf(mx, fmaxf(accS[nf][half * 2], accS[nf][half * 2 + 1]));
            mx = fmaxf(mx, __shfl_xor_sync(0xffffffffu, mx, 1));
            mx = fmaxf(mx, __shfl_xor_sync(0xffffffffu, mx, 2));
            const float mnew = fmaxf(m[half], mx);
            const float corr = __expf(m[half] - mnew);
            m[half] = mnew;
            float ps = 0.f;
#pragma unroll
            for (int nf = 0; nf < 16; nf++) {
                const float p0 = __expf(accS[nf][half * 2] - mnew);
                const float p1 = __expf(accS[nf][half * 2 + 1] - mnew);
                accS[nf][half * 2] = p0;
                accS[nf][half * 2 + 1] = p1;
                ps += p0 + p1;
            }
            ps += __shfl_xor_sync(0xffffffffu, ps, 1);
            ps += __shfl_xor_sync(0xffffffffu, ps, 2);
            l[half] = l[half] * corr + ps;
#pragma unroll
            for (int nf = 0; nf < 8; nf++) {
                accO[nf][half * 2] *= corr;
                accO[nf][half * 2 + 1] *= corr;
            }
        }

#pragma unroll
        for (int ks2 = 0; ks2 < 8; ks2++) {
            uint32_t pah[4], pal[4];
            split2(accS[2 * ks2][0], accS[2 * ks2][1], pah[0], pal[0]);
            split2(accS[2 * ks2][2], accS[2 * ks2][3], pah[1], pal[1]);
            split2(accS[2 * ks2 + 1][0], accS[2 * ks2 + 1][1], pah[2], pal[2]);
            split2(accS[2 * ks2 + 1][2], accS[2 * ks2 + 1][3], pah[3], pal[3]);
            const uint32_t sub = (ks2 >> 2) * 8192;
            const uint32_t kb2 = (ks2 & 3) * 32 + kbl;
#pragma unroll
            for (int np = 0; np < 4; np++) {
                uint32_t vh[4], vl[4];
                const uint32_t voff = sub + SW128((uint32_t)((np * 16 + lrow) * 128) + kb2);
                ldsm4(vh, smV + voff);
                ldsm4(vl, smV + 16384 + voff);
#pragma unroll
                for (int sel = 0; sel < 2; sel++) {
                    const int nf2 = np * 2 + sel;
                    mma16816(accO[nf2], pah, vh[sel], vh[sel + 2]);
                    mma16816(accO[nf2], pah, vl[sel], vl[sel + 2]);
                    mma16816(accO[nf2], pal, vh[sel], vh[sel + 2]);
                }
            }
        }
    }

    if ((lane & 3) == 0) {
        g_am[b][chunk][it][m0 + rr] = m[0];
        g_am[b][chunk][it][m0 + 8 + rr] = m[1];
        g_al[b][chunk][it][m0 + rr] = l[0];
        g_al[b][chunk][it][m0 + 8 + rr] = l[1];
    }
    float* aO = g_aO[b][chunk][it];
#pragma unroll
    for (int nf = 0; nf < 8; nf++) {
        const int gc = nf * 8 + cc;
        *(float2*)(aO + (m0 + rr) * 64 + gc) = make_float2(accO[nf][0], accO[nf][1]);
        *(float2*)(aO + (m0 + 8 + rr) * 64 + gc) = make_float2(accO[nf][2], accO[nf][3]);
    }
}

// ---------------------------------------------------------------------------
// K5: combine split-KV partials.  grid (16 it, 4 b), 256 thr.
// ---------------------------------------------------------------------------
__global__ void k_comb(float* __restrict__ out) {
    const int it = blockIdx.x, b = blockIdx.y;
    const int nch = it / 2 + 1;
    const int tid = threadIdx.x;
    const int r = tid >> 1;
    const int c0 = (tid & 1) * 32;

    float M = -1e30f;
#pragma unroll
    for (int c = 0; c < 8; c++)
        if (c < nch) M = fmaxf(M, g_am[b][c][it][r]);

    float w[8];
    float lt = 0.f;
#pragma unroll
    for (int c = 0; c < 8; c++) {
        w[c] = 0.f;
        if (c < nch) {
            w[c] = __expf(g_am[b][c][it][r] - M);
            lt += g_al[b][c][it][r] * w[c];
        }
    }
    const float inv = 1.f / lt;

    float* dst = out + ((size_t)b * SS + it * 128 + r) * DHE + c0;
#pragma unroll
    for (int j4 = 0; j4 < 8; j4++) {
        float4 acc = make_float4(0.f, 0.f, 0.f, 0.f);
#pragma unroll
        for (int c = 0; c < 8; c++)
            if (c < nch) {
                float4 v = *(const float4*)&g_aO[b][c][it][r * 64 + c0 + j4 * 4];
                acc.x = fmaf(v.x, w[c], acc.x);
                acc.y = fmaf(v.y, w[c], acc.y);
                acc.z = fmaf(v.z, w[c], acc.z);
                acc.w = fmaf(v.w, w[c], acc.w);
            }
        *(float4*)(dst + j4 * 4) =
            make_float4(acc.x * inv, acc.y * inv, acc.z * inv, acc.w * inv);
    }
}

// ---------------------------------------------------------------------------
extern "C" void kernel_launch(void* const* d_in, const int* in_sizes, int n_in,
                              void* d_out, int out_size) {
    const float* x   = (const float*)d_in[0];
    const float* wqu = (const float*)d_in[1];
    const float* wku = (const float*)d_in[2];
    const float* wvu = (const float*)d_in[3];
    const float* wqc = (const float*)d_in[4];
    const float* wkc = (const float*)d_in[5];
    const float* wvc = (const float*)d_in[6];
    float* out = (float*)d_out;

    k_cvt<<<2048, 256>>>(x, wqu, wku, wvu, wqc, wkc, wvc);

    const int proj_smem = 1024 + 2 * 49152;  // 99328 B
    cudaFuncSetAttribute(k_proj_mma, cudaFuncAttributeMaxDynamicSharedMemorySize, proj_smem);
    k_proj_mma<<<dim3(64, 6), 256, proj_smem>>>();

    k_vt<<<dim3(64, 4), 256>>>();

    const int pair_smem = 1024 + 65536;  // 66560 B
    cudaFuncSetAttribute(k_pair_mma, cudaFuncAttributeMaxDynamicSharedMemorySize, pair_smem);
    k_pair_mma<<<dim3(136, 4, 2), 256, pair_smem>>>();

    const int su_smem = 1024 + 3 * 65536;  // 197632 B (3-stage)
    cudaFuncSetAttribute(k_su_mma, cudaFuncAttributeMaxDynamicSharedMemorySize, su_smem);
    k_su_mma<<<dim3(272, 1, 4), 256, su_smem>>>();

    const int attn_smem = 1024 + 6 * 16384;  // 99328 B
    cudaFuncSetAttribute(k_attn_mma, cudaFuncAttributeMaxDynamicSharedMemorySize, attn_smem);
    k_attn_mma<<<dim3(16, 8, 4), 256, attn_smem>>>();

    k_comb<<<dim3(16, 4), 256>>>(out);
}

// round 14
// speedup vs baseline: 1.0086x; 1.0086x over previous
#include <cuda_runtime.h>
#include <cuda_bf16.h>
#include <cstdint>

#define BB 4
#define SS 2048
#define DD 1024
#define DHE 64
#define SCALE 0.125f

// ---------------- scratch (device globals) ----------------
static __device__ float g_P[6][BB * SS * DHE];  // only [5]=Vc used in f32
static __device__ __nv_bfloat16 g_Ph[5][BB * SS * DHE];  // hi of Qu,Ku,Vu,Qc,Kc
static __device__ __nv_bfloat16 g_Pl[5][BB * SS * DHE];  // lo
static __device__ __nv_bfloat16 g_Vth[(size_t)BB * DHE * SS];  // Vc^T [b][d][s]
static __device__ __nv_bfloat16 g_Vtl[(size_t)BB * DHE * SS];
static __device__ __nv_bfloat16 g_xh[(size_t)BB * SS * DD];
static __device__ __nv_bfloat16 g_xl[(size_t)BB * SS * DD];
static __device__ __nv_bfloat16 g_wh[6][DHE * DD];  // [head][n][k]
static __device__ __nv_bfloat16 g_wl[6][DHE * DD];
static __device__ __nv_bfloat16 g_t1h[(size_t)BB * SS * SS];
static __device__ __nv_bfloat16 g_t1l[(size_t)BB * SS * SS];
static __device__ __nv_bfloat16 g_sgh[(size_t)BB * SS * SS];
static __device__ __nv_bfloat16 g_sgl[(size_t)BB * SS * SS];
static __device__ float g_suA[(size_t)BB * SS * SS];
static __device__ float g_suB[(size_t)BB * SS * SS];
// split-KV partials: 8 chunks (2 k-tiles of 128 each), 16 i-tiles of 128 rows
static __device__ float g_am[BB][8][16][128];
static __device__ float g_al[BB][8][16][128];
static __device__ float g_aO[BB][8][16][128 * 64];

// ---------------- helpers (compute_103-safe) ----------------
__device__ __forceinline__ uint32_t smem_to_u32(const void* p) {
    uint32_t a;
    asm("{ .reg .u64 t; cvta.to.shared.u64 t, %1; cvt.u32.u64 %0, t; }" : "=r"(a) : "l"(p));
    return a;
}
#define SW128(o) ((o) ^ (((o) >> 3) & 0x70))

__device__ __forceinline__ void ldsm4(uint32_t* r, uint32_t addr) {
    asm volatile("ldmatrix.sync.aligned.m8n8.x4.shared.b16 {%0,%1,%2,%3}, [%4];"
        : "=r"(r[0]), "=r"(r[1]), "=r"(r[2]), "=r"(r[3]) : "r"(addr));
}
__device__ __forceinline__ void mma16816(float* c, const uint32_t* a,
                                         uint32_t b0, uint32_t b1) {
    asm volatile("mma.sync.aligned.m16n8k16.row.col.f32.bf16.bf16.f32 "
        "{%0,%1,%2,%3}, {%4,%5,%6,%7}, {%8,%9}, {%0,%1,%2,%3};"
        : "+f"(c[0]), "+f"(c[1]), "+f"(c[2]), "+f"(c[3])
        : "r"(a[0]), "r"(a[1]), "r"(a[2]), "r"(a[3]), "r"(b0), "r"(b1));
}

__device__ __forceinline__ float fast_rcp(float y) {
    float r = __int_as_float(0x7EF127EAu - __float_as_int(y));
    r = r * fmaf(-y, r, 2.0f);
    r = r * fmaf(-y, r, 2.0f);
    r = r * fmaf(-y, r, 2.0f);
    return r;
}
__device__ __forceinline__ float fast_sigmoid(float x) {
    const float t = __expf(-fmaxf(x, -80.f));
    return fast_rcp(1.f + t);
}
__device__ __forceinline__ float fast_silu(float x) {
    return x * fast_sigmoid(x);
}
__device__ __forceinline__ void split2(float v0, float v1, uint32_t& h, uint32_t& l) {
    const __nv_bfloat16 h0 = __float2bfloat16(v0), h1 = __float2bfloat16(v1);
    const __nv_bfloat16 l0 = __float2bfloat16(v0 - __bfloat162float(h0));
    const __nv_bfloat16 l1 = __float2bfloat16(v1 - __bfloat162float(h1));
    union { __nv_bfloat162 b; uint32_t u; } H, L;
    H.b = __halves2bfloat162(h0, h1);
    L.b = __halves2bfloat162(l0, l1);
    h = H.u; l = L.u;
}

// ---------------------------------------------------------------------------
// K0: convert x AND weights -> bf16 hi/lo (merged, one launch)
// ---------------------------------------------------------------------------
__global__ void k_cvt(const float* __restrict__ x,
                      const float* __restrict__ w0, const float* __restrict__ w1,
                      const float* __restrict__ w2, const float* __restrict__ w3,
                      const float* __restrict__ w4, const float* __restrict__ w5) {
    const size_t n_x = (size_t)BB * SS * DD;
    const size_t n_w = 6 * DD * DHE;
    const size_t n = n_x + n_w;
    for (size_t i = (size_t)blockIdx.x * blockDim.x + threadIdx.x; i < n;
         i += (size_t)gridDim.x * blockDim.x) {
        if (i < n_x) {
            const float v = x[i];
            const __nv_bfloat16 h = __float2bfloat16(v);
            g_xh[i] = h;
            g_xl[i] = __float2bfloat16(v - __bfloat162float(h));
        } else {
            const int j = (int)(i - n_x);
            const int head = j >> 16;
            const int rem = j & 65535;
            const int k = rem >> 6, nn = rem & 63;
            const float* w = head == 0 ? w0 : head == 1 ? w1 : head == 2 ? w2
                           : head == 3 ? w3 : head == 4 ? w4 : w5;
            const float v = w[k * DHE + nn];
            const __nv_bfloat16 h = __float2bfloat16(v);
            g_wh[head][nn * DD + k] = h;
            g_wl[head][nn * DD + k] = __float2bfloat16(v - __bfloat162float(h));
        }
    }
}

// ---------------------------------------------------------------------------
// K1: projections via mma.sync bf16 hi/lo.  out[h] = x @ w[h].
// MMA passes product-outermost (acc reuse distance 8).
// ---------------------------------------------------------------------------
__global__ void __launch_bounds__(256) k_proj_mma() {
    extern __shared__ char smem[];
    const uint32_t tiles = (smem_to_u32(smem) + 1023u) & ~1023u;
    const int row0 = blockIdx.x * 128, head = blockIdx.y;

    const int tid = threadIdx.x;
    const int wid = tid >> 5, lane = tid & 31;
    const int wm = wid & 3, wn = wid >> 2;
    const int lrow = lane & 15;
    const uint32_t kbl = (lane >> 4) * 16;

#define PJ_LOAD(stage, ch) do { \
    const uint32_t _st = tiles + (stage) * 49152; \
    _Pragma("unroll") \
    for (int q = 0; q < 4; q++) { \
        const int r = (tid >> 3) + q * 32; \
        const int c16 = tid & 7; \
        const uint32_t so = SW128((uint32_t)(r * 128 + c16 * 16)); \
        const size_t go = (size_t)(row0 + r) * DD + (ch) + c16 * 8; \
        asm volatile("cp.async.cg.shared.global [%0], [%1], 16;" :: "r"(_st + so), "l"(g_xh + go)); \
        asm volatile("cp.async.cg.shared.global [%0], [%1], 16;" :: "r"(_st + 16384 + so), "l"(g_xl + go)); \
    } \
    _Pragma("unroll") \
    for (int q = 0; q < 2; q++) { \
        const int r = (tid >> 3) + q * 32; \
        const int c16 = tid & 7; \
        const uint32_t so = SW128((uint32_t)(r * 128 + c16 * 16)); \
        const size_t go = (size_t)r * DD + (ch) + c16 * 8; \
        asm volatile("cp.async.cg.shared.global [%0], [%1], 16;" :: "r"(_st + 32768 + so), "l"(g_wh[head] + go)); \
        asm volatile("cp.async.cg.shared.global [%0], [%1], 16;" :: "r"(_st + 40960 + so), "l"(g_wl[head] + go)); \
    } \
    asm volatile("cp.async.commit_group;"); \
} while (0)

    float acc[2][4][4];
#pragma unroll
    for (int mf = 0; mf < 2; mf++)
#pragma unroll
        for (int nf = 0; nf < 4; nf++)
#pragma unroll
            for (int q = 0; q < 4; q++) acc[mf][nf][q] = 0.f;

    PJ_LOAD(0, 0);

    for (int c = 0; c < DD / 64; c++) {
        const int s = c & 1;
        if (c + 1 < DD / 64) {
            PJ_LOAD(s ^ 1, (c + 1) * 64);
            asm volatile("cp.async.wait_group 1;");
        } else {
            asm volatile("cp.async.wait_group 0;");
        }
        __syncthreads();

        const uint32_t stAh = tiles + s * 49152;
        const uint32_t stAl = stAh + 16384;
        const uint32_t stBh = stAh + 32768;
        const uint32_t stBl = stAh + 40960;

#pragma unroll
        for (int ks = 0; ks < 4; ks++) {
            const uint32_t kb = ks * 32 + kbl;
            uint32_t ah[2][4], al[2][4], bh[2][4], bl[2][4];
#pragma unroll
            for (int mf = 0; mf < 2; mf++) {
                const uint32_t off = SW128((uint32_t)((wm * 32 + mf * 16 + lrow) * 128) + kb);
                ldsm4(ah[mf], stAh + off);
                ldsm4(al[mf], stAl + off);
            }
#pragma unroll
            for (int np = 0; np < 2; np++) {
                const uint32_t off = SW128((uint32_t)((wn * 32 + np * 16 + lrow) * 128) + kb);
                ldsm4(bh[np], stBh + off);
                ldsm4(bl[np], stBl + off);
            }
            // pass 1: hh
#pragma unroll
            for (int mf = 0; mf < 2; mf++)
#pragma unroll
                for (int nf = 0; nf < 4; nf++) {
                    const int np = nf >> 1, sel = nf & 1;
                    mma16816(acc[mf][nf], ah[mf], bh[np][sel], bh[np][sel + 2]);
                }
            // pass 2: hl
#pragma unroll
            for (int mf = 0; mf < 2; mf++)
#pragma unroll
                for (int nf = 0; nf < 4; nf++) {
                    const int np = nf >> 1, sel = nf & 1;
                    mma16816(acc[mf][nf], ah[mf], bl[np][sel], bl[np][sel + 2]);
                }
            // pass 3: lh
#pragma unroll
            for (int mf = 0; mf < 2; mf++)
#pragma unroll
                for (int nf = 0; nf < 4; nf++) {
                    const int np = nf >> 1, sel = nf & 1;
                    mma16816(acc[mf][nf], al[mf], bh[np][sel], bh[np][sel + 2]);
                }
        }
        __syncthreads();
    }
#undef PJ_LOAD

    const int rr = lane >> 2, cc = (lane & 3) * 2;
    if (head == 5) {
        float* C = g_P[5];
#pragma unroll
        for (int mf = 0; mf < 2; mf++) {
            const int gr = row0 + wm * 32 + mf * 16 + rr;
#pragma unroll
            for (int nf = 0; nf < 4; nf++) {
                const int gc = wn * 32 + nf * 8 + cc;
                *(float2*)(C + (size_t)gr * DHE + gc) = make_float2(acc[mf][nf][0], acc[mf][nf][1]);
                *(float2*)(C + (size_t)(gr + 8) * DHE + gc) = make_float2(acc[mf][nf][2], acc[mf][nf][3]);
            }
        }
    } else {
        __nv_bfloat16* Hh = g_Ph[head];
        __nv_bfloat16* Hl = g_Pl[head];
#pragma unroll
        for (int mf = 0; mf < 2; mf++) {
            const int gr = row0 + wm * 32 + mf * 16 + rr;
#pragma unroll
            for (int nf = 0; nf < 4; nf++) {
                const int gc = wn * 32 + nf * 8 + cc;
                uint32_t h0, l0, h1, l1;
                split2(acc[mf][nf][0], acc[mf][nf][1], h0, l0);
                split2(acc[mf][nf][2], acc[mf][nf][3], h1, l1);
                *(uint32_t*)(Hh + (size_t)gr * DHE + gc) = h0;
                *(uint32_t*)(Hl + (size_t)gr * DHE + gc) = l0;
                *(uint32_t*)(Hh + (size_t)(gr + 8) * DHE + gc) = h1;
                *(uint32_t*)(Hl + (size_t)(gr + 8) * DHE + gc) = l1;
            }
        }
    }
}

// ---------------------------------------------------------------------------
// K1b: transpose Vc -> [b][d][s] bf16 hi/lo.  grid (64 s-tiles of 32, 4 b).
// ---------------------------------------------------------------------------
__global__ void k_vt() {
    __shared__ float ts[32][65];
    const int s0 = blockIdx.x * 32, b = blockIdx.y;
    const int tid = threadIdx.x;
    for (int t = tid; t < 2048; t += 256) {
        const int r = t >> 6, c = t & 63;
        ts[r][c] = g_P[5][((size_t)b * SS + s0 + r) * DHE + c];
    }
    __syncthreads();
    for (int t = tid; t < 2048; t += 256) {
        const int d = t >> 5, sc = t & 31;
        const float v = ts[sc][d];
        const __nv_bfloat16 h = __float2bfloat16(v);
        const size_t o = ((size_t)b * DHE + d) * SS + s0 + sc;
        g_Vth[o] = h;
        g_Vtl[o] = __float2bfloat16(v - __bfloat162float(h));
    }
}

// ---------------------------------------------------------------------------
// K2: term1 / sigmoid gate via mma.sync, 128x128 tiles.
// MMA passes product-outermost (acc reuse distance 16).
// grid (136 tri-pairs, 4 b, 2 modes), 256 thr, 66560 B smem.
// ---------------------------------------------------------------------------
__global__ void __launch_bounds__(256) k_pair_mma() {
    extern __shared__ char smem[];
    const uint32_t tiles = (smem_to_u32(smem) + 1023u) & ~1023u;

    const int mode = blockIdx.z, b = blockIdx.y;
    int pp = blockIdx.x;
    int d = 15;
    while (pp >= 16 - d) { pp -= 16 - d; d--; }
    const int rt = (mode == 0) ? (pp + d) : pp;
    const int ct = (mode == 0) ? pp : (pp + d);
    const int i0 = rt * 128, j0 = ct * 128;
    const int hA = (mode == 0) ? 3 : 0;
    const int hB = (mode == 0) ? 2 : 1;

    const int tid = threadIdx.x;
    const int wid = tid >> 5, lane = tid & 31;

    {
        const int ltile = tid >> 6;
        const int llane = tid & 63;
        const int rl = llane >> 3, c16 = llane & 7;
        const __nv_bfloat16* src =
            (ltile == 0) ? g_Ph[hA] + ((size_t)b * SS + i0) * DHE :
            (ltile == 1) ? g_Pl[hA] + ((size_t)b * SS + i0) * DHE :
            (ltile == 2) ? g_Ph[hB] + ((size_t)b * SS + j0) * DHE :
                           g_Pl[hB] + ((size_t)b * SS + j0) * DHE;
        const __nv_bfloat16* g = src + (size_t)rl * DHE + c16 * 8;
        const uint32_t tsm = tiles + ltile * 16384;
#pragma unroll
        for (int q = 0; q < 16; q++) {
            const uint32_t so = SW128((uint32_t)((q * 8 + rl) * 128 + c16 * 16));
            asm volatile("cp.async.cg.shared.global [%0], [%1], 16;"
                :: "r"(tsm + so), "l"(g + (size_t)q * 8 * DHE));
        }
        asm volatile("cp.async.commit_group;");
        asm volatile("cp.async.wait_group 0;");
    }
    __syncthreads();

    float acc[2][8][4];
#pragma unroll
    for (int mf = 0; mf < 2; mf++)
#pragma unroll
        for (int nf = 0; nf < 8; nf++)
#pragma unroll
            for (int q = 0; q < 4; q++) acc[mf][nf][q] = 0.f;

    const int wm = wid >> 1, wn = wid & 1;
    const int lrow = lane & 15;
    const uint32_t kbl = (lane >> 4) * 16;
    const uint32_t stAh = tiles, stAl = tiles + 16384;
    const uint32_t stBh = tiles + 32768, stBl = tiles + 49152;

#pragma unroll
    for (int ks = 0; ks < 4; ks++) {
        const uint32_t kb = ks * 32 + kbl;
        uint32_t ah[2][4], al[2][4], bh[4][4], bl[4][4];
#pragma unroll
        for (int mf = 0; mf < 2; mf++) {
            const uint32_t off = SW128((uint32_t)((wm * 32 + mf * 16 + lrow) * 128) + kb);
            ldsm4(ah[mf], stAh + off);
            ldsm4(al[mf], stAl + off);
        }
#pragma unroll
        for (int np = 0; np < 4; np++) {
            const uint32_t off = SW128((uint32_t)((wn * 64 + np * 16 + lrow) * 128) + kb);
            ldsm4(bh[np], stBh + off);
            ldsm4(bl[np], stBl + off);
        }
        // pass 1: hh
#pragma unroll
        for (int mf = 0; mf < 2; mf++)
#pragma unroll
            for (int nf = 0; nf < 8; nf++) {
                const int np = nf >> 1, sel = nf & 1;
                mma16816(acc[mf][nf], ah[mf], bh[np][sel], bh[np][sel + 2]);
            }
        // pass 2: hl
#pragma unroll
        for (int mf = 0; mf < 2; mf++)
#pragma unroll
            for (int nf = 0; nf < 8; nf++) {
                const int np = nf >> 1, sel = nf & 1;
                mma16816(acc[mf][nf], ah[mf], bl[np][sel], bl[np][sel + 2]);
            }
        // pass 3: lh
#pragma unroll
        for (int mf = 0; mf < 2; mf++)
#pragma unroll
            for (int nf = 0; nf < 8; nf++) {
                const int np = nf >> 1, sel = nf & 1;
                mma16816(acc[mf][nf], al[mf], bh[np][sel], bh[np][sel + 2]);
            }
    }

    const size_t boff = (size_t)b * SS * SS;
    __nv_bfloat16* outh = (mode == 0 ? g_t1h : g_sgh) + boff;
    __nv_bfloat16* outl = (mode == 0 ? g_t1l : g_sgl) + boff;
    const int rr = lane >> 2, cc = (lane & 3) * 2;
#pragma unroll
    for (int mf = 0; mf < 2; mf++) {
#pragma unroll
        for (int half = 0; half < 2; half++) {
            const int gi = i0 + wm * 32 + mf * 16 + half * 8 + rr;
#pragma unroll
            for (int nf = 0; nf < 8; nf++) {
                const int gc = j0 + wn * 64 + nf * 8 + cc;
                float v0 = acc[mf][nf][half * 2 + 0] * SCALE;
                float v1 = acc[mf][nf][half * 2 + 1] * SCALE;
                if (mode == 0) {
                    v0 = (gc <= gi) ? v0 : 0.f;
                    v1 = (gc + 1 <= gi) ? v1 : 0.f;
                } else {
                    v0 = (gc > gi) ? fast_sigmoid(v0) : 0.f;
                    v1 = (gc + 1 > gi) ? fast_sigmoid(v1) : 0.f;
                }
                uint32_t h, l;
                split2(v0, v1, h, l);
                *(uint32_t*)(outh + (size_t)gi * SS + gc) = h;
                *(uint32_t*)(outl + (size_t)gi * SS + gc) = l;
            }
        }
    }
}

// ---------------------------------------------------------------------------
// K3: S_u via mma.sync bf16x2-split, j-SPLIT, 2-stage pipeline,
// MMA passes product-outermost (acc reuse distance 16).
// grid (272, 1, 4 b), 256 thr, 132096 B smem.
// ---------------------------------------------------------------------------
__global__ void __launch_bounds__(256) k_su_mma() {
    extern __shared__ char smem[];
    const uint32_t tiles = (smem_to_u32(smem) + 1023u) & ~1023u;

    const int b = blockIdx.z;
    const int seg = blockIdx.x & 1;
    int pp = blockIdx.x >> 1;
    int d = 15;
    while (pp >= 16 - d) { pp -= 16 - d; d--; }
    const int kt = pp, it = pp + d;
    const int i0 = it * 128, k0 = kt * 128;

    int jbeg = k0, jend = (it + 1) * 128;
    const int mid = jbeg + ((jend - jbeg) >> 1);
    if (seg == 0) jend = mid; else jbeg = mid;
    const int nch = (jend - jbeg) >> 6;

    const int tid = threadIdx.x;
    const int wid = tid >> 5, lane = tid & 31;

    const int ltile = tid >> 6;
    const int llane = tid & 63;
    const int rl = llane >> 3;
    const int c16 = llane & 7;
    const size_t boff = (size_t)b * SS * SS;
    const __nv_bfloat16* src =
        (ltile == 0) ? g_t1h + boff + (size_t)i0 * SS :
        (ltile == 1) ? g_t1l + boff + (size_t)i0 * SS :
        (ltile == 2) ? g_sgh + boff + (size_t)k0 * SS :
                       g_sgl + boff + (size_t)k0 * SS;
    const __nv_bfloat16* gbase = src + (size_t)rl * SS + c16 * 8;
    const uint32_t tsm = tiles + ltile * 16384;

#define SU_LOAD_CHUNK(stage, j0v) do { \
    const __nv_bfloat16* _g = gbase + (j0v); \
    const uint32_t _base = tsm + (stage) * 65536; \
    _Pragma("unroll") \
    for (int q = 0; q < 16; q++) { \
        uint32_t so = (uint32_t)((q * 8 + rl) * 128 + c16 * 16); \
        uint32_t sa = _base + SW128(so); \
        asm volatile("cp.async.cg.shared.global [%0], [%1], 16;" :: "r"(sa), "l"(_g + (size_t)q * 8 * SS)); \
    } \
    asm volatile("cp.async.commit_group;"); \
} while (0)

    float acc[2][8][4];
#pragma unroll
    for (int mf = 0; mf < 2; mf++)
#pragma unroll
        for (int nf = 0; nf < 8; nf++)
#pragma unroll
            for (int q = 0; q < 4; q++) acc[mf][nf][q] = 0.f;

    const int wm = wid >> 1, wn = wid & 1;
    const int lrow = lane & 15;
    const uint32_t kbl = (lane >> 4) * 16;

    SU_LOAD_CHUNK(0, jbeg);

    for (int i = 0; i < nch; i++) {
        const int s = i & 1;
        if (i + 1 < nch) {
            SU_LOAD_CHUNK(s ^ 1, jbeg + (i + 1) * 64);
            asm volatile("cp.async.wait_group 1;");
        } else {
            asm volatile("cp.async.wait_group 0;");
        }
        __syncthreads();

        const uint32_t stAh = tiles + s * 65536;
        const uint32_t stAl = stAh + 16384;
        const uint32_t stBh = stAh + 32768;
        const uint32_t stBl = stAh + 49152;

#pragma unroll
        for (int ks = 0; ks < 4; ks++) {
            const uint32_t kb = ks * 32 + kbl;
            uint32_t ah[2][4], al[2][4], bh[4][4], bl[4][4];
#pragma unroll
            for (int mf = 0; mf < 2; mf++) {
                const uint32_t off = SW128((uint32_t)((wm * 32 + mf * 16 + lrow) * 128) + kb);
                ldsm4(ah[mf], stAh + off);
                ldsm4(al[mf], stAl + off);
            }
#pragma unroll
            for (int np = 0; np < 4; np++) {
                const uint32_t off = SW128((uint32_t)((wn * 64 + np * 16 + lrow) * 128) + kb);
                ldsm4(bh[np], stBh + off);
                ldsm4(bl[np], stBl + off);
            }
            // pass 1: hh
#pragma unroll
            for (int mf = 0; mf < 2; mf++)
#pragma unroll
                for (int nf = 0; nf < 8; nf++) {
                    const int np = nf >> 1, sel = nf & 1;
                    mma16816(acc[mf][nf], ah[mf], bh[np][sel], bh[np][sel + 2]);
                }
            // pass 2: hl
#pragma unroll
            for (int mf = 0; mf < 2; mf++)
#pragma unroll
                for (int nf = 0; nf < 8; nf++) {
                    const int np = nf >> 1, sel = nf & 1;
                    mma16816(acc[mf][nf], ah[mf], bl[np][sel], bl[np][sel + 2]);
                }
            // pass 3: lh
#pragma unroll
            for (int mf = 0; mf < 2; mf++)
#pragma unroll
                for (int nf = 0; nf < 8; nf++) {
                    const int np = nf >> 1, sel = nf & 1;
                    mma16816(acc[mf][nf], al[mf], bh[np][sel], bh[np][sel + 2]);
                }
        }
        __syncthreads();
    }
#undef SU_LOAD_CHUNK

    float* C = (seg ? g_suB : g_suA) + boff;
    const int rr = lane >> 2, cc = (lane & 3) * 2;
#pragma unroll
    for (int mf = 0; mf < 2; mf++) {
        const int gr = i0 + wm * 32 + mf * 16 + rr;
#pragma unroll
        for (int nf = 0; nf < 8; nf++) {
            const int gc = k0 + wn * 64 + nf * 8 + cc;
            *(float2*)(C + (size_t)gr * SS + gc) = make_float2(acc[mf][nf][0], acc[mf][nf][1]);
            *(float2*)(C + (size_t)(gr + 8) * SS + gc) = make_float2(acc[mf][nf][2], acc[mf][nf][3]);
        }
    }
}

// ---------------------------------------------------------------------------
// K4: flash attention partial via mma.sync (2 k-tiles per chunk).
// Sc and PV MMA passes product-outermost within B-fragment groups.
// grid (16 it, 8 chunk, 4 b), 256 thr, 99328 B smem.
// ---------------------------------------------------------------------------
__global__ void __launch_bounds__(256) k_attn_mma() {
    const int it = blockIdx.x, chunk = blockIdx.y, b = blockIdx.z;
    if (chunk * 2 > it) return;
    const int kt_beg = chunk * 2;
    const int kt_end = min(kt_beg + 2, it + 1);
    const int i0 = it * 128;

    extern __shared__ char smem[];
    const uint32_t sb = (smem_to_u32(smem) + 1023u) & ~1023u;
    const uint32_t smQ = sb;
    const uint32_t smK = sb + 32768;
    const uint32_t smV = sb + 65536;

    const int tid = threadIdx.x;
    const int wid = tid >> 5, lane = tid & 31;
    const int m0 = wid * 16;
    const int lrow = lane & 15;
    const uint32_t kbl = (lane >> 4) * 16;
    const int rr = lane >> 2, cc = (lane & 3) * 2;

    for (int t = tid; t < 2048; t += 256) {
        const int half = t >> 10, r = (t >> 3) & 127, c16 = t & 7;
        const __nv_bfloat16* src = (half ? g_Pl[3] : g_Ph[3])
            + ((size_t)b * SS + i0 + r) * DHE + c16 * 8;
        const uint32_t dst = smQ + half * 16384 + SW128((uint32_t)(r * 128 + c16 * 16));
        asm volatile("cp.async.cg.shared.global [%0], [%1], 16;" :: "r"(dst), "l"(src));
    }
    asm volatile("cp.async.commit_group;");

    const float* SuA = g_suA + (size_t)b * SS * SS;
    const float* SuB = g_suB + (size_t)b * SS * SS;

    float m[2] = {-1e30f, -1e30f}, l[2] = {0.f, 0.f};
    float accO[8][4];
#pragma unroll
    for (int nf = 0; nf < 8; nf++)
#pragma unroll
        for (int q = 0; q < 4; q++) accO[nf][q] = 0.f;

    for (int kt = kt_beg; kt < kt_end; kt++) {
        const int k0t = kt * 128;
        __syncthreads();
        for (int t = tid; t < 2048; t += 256) {
            const int half = t >> 10, r = (t >> 3) & 127, c16 = t & 7;
            const __nv_bfloat16* src = (half ? g_Pl[4] : g_Ph[4])
                + ((size_t)b * SS + k0t + r) * DHE + c16 * 8;
            const uint32_t dst = smK + half * 16384 + SW128((uint32_t)(r * 128 + c16 * 16));
            asm volatile("cp.async.cg.shared.global [%0], [%1], 16;" :: "r"(dst), "l"(src));
        }
        for (int t = tid; t < 2048; t += 256) {
            const int half = t >> 10, rw = (t >> 3) & 127, c16 = t & 7;
            const int dd = rw & 63, sub = rw >> 6;
            const __nv_bfloat16* src = (half ? g_Vtl : g_Vth)
                + ((size_t)b * DHE + dd) * SS + k0t + sub * 64 + c16 * 8;
            const uint32_t dst = smV + half * 16384 + sub * 8192
                + SW128((uint32_t)(dd * 128 + c16 * 16));
            asm volatile("cp.async.cg.shared.global [%0], [%1], 16;" :: "r"(dst), "l"(src));
        }
        asm volatile("cp.async.commit_group;");
        asm volatile("cp.async.wait_group 0;");
        __syncthreads();

        float accS[16][4];
#pragma unroll
        for (int nf = 0; nf < 16; nf++)
#pragma unroll
            for (int q = 0; q < 4; q++) accS[nf][q] = 0.f;

#pragma unroll
        for (int ks = 0; ks < 4; ks++) {
            const uint32_t kb = ks * 32 + kbl;
            uint32_t ah[4], al[4];
            const uint32_t aoff = SW128((uint32_t)((m0 + lrow) * 128) + kb);
            ldsm4(ah, smQ + aoff);
            ldsm4(al, smQ + 16384 + aoff);
#pragma unroll
            for (int g = 0; g < 2; g++) {
                uint32_t bh[4][4], bl[4][4];
#pragma unroll
                for (int n4 = 0; n4 < 4; n4++) {
                    const int np = g * 4 + n4;
                    const uint32_t boffs = SW128((uint32_t)((np * 16 + lrow) * 128) + kb);
                    ldsm4(bh[n4], smK + boffs);
                    ldsm4(bl[n4], smK + 16384 + boffs);
                }
                // pass 1: hh
#pragma unroll
                for (int n4 = 0; n4 < 4; n4++)
#pragma unroll
                    for (int sel = 0; sel < 2; sel++)
                        mma16816(accS[(g * 4 + n4) * 2 + sel], ah, bh[n4][sel], bh[n4][sel + 2]);
                // pass 2: hl
#pragma unroll
                for (int n4 = 0; n4 < 4; n4++)
#pragma unroll
                    for (int sel = 0; sel < 2; sel++)
                        mma16816(accS[(g * 4 + n4) * 2 + sel], ah, bl[n4][sel], bl[n4][sel + 2]);
                // pass 3: lh
#pragma unroll
                for (int n4 = 0; n4 < 4; n4++)
#pragma unroll
                    for (int sel = 0; sel < 2; sel++)
                        mma16816(accS[(g * 4 + n4) * 2 + sel], al, bh[n4][sel], bh[n4][sel + 2]);
            }
        }

        const bool diag = (kt == it);
#pragma unroll
        for (int nf = 0; nf < 16; nf++) {
            const int gk = k0t + nf * 8 + cc;
#pragma unroll
            for (int half = 0; half < 2; half++) {
                const int gi = i0 + m0 + half * 8 + rr;
                const float2 a2 = *(const float2*)(SuA + (size_t)gi * SS + gk);
                const float2 b2 = *(const float2*)(SuB + (size_t)gi * SS + gk);
                float v0 = accS[nf][half * 2 + 0] * SCALE - fast_silu(a2.x + b2.x);
                float v1 = accS[nf][half * 2 + 1] * SCALE - fast_silu(a2.y + b2.y);
                if (diag) {
                    if (gk > gi) v0 = -1e30f;
                    if (gk + 1 > gi) v1 = -1e30f;
                }
                accS[nf][half * 2 + 0] = v0;
                accS[nf][half * 2 + 1] = v1;
            }
        }

#pragma unroll
        for (int half = 0; half < 2; half++) {
            float mx = -1e30f;
#pragma unroll
            for (int nf = 0; nf < 16; nf++)
                mx = fmaxf(mx, fmaxf(accS[nf][half * 2], accS[nf][half * 2 + 1]));
            mx = fmaxf(mx, __shfl_xor_sync(0xffffffffu, mx, 1));
            mx = fmaxf(mx, __shfl_xor_sync(0xffffffffu, mx, 2));
            const float mnew = fmaxf(m[half], mx);
            const float corr = __expf(m[half] - mnew);
            m[half] = mnew;
            float ps = 0.f;
#pragma unroll
            for (int nf = 0; nf < 16; nf++) {
                const float p0 = __expf(accS[nf][half * 2] - mnew);
                const float p1 = __expf(accS[nf][half * 2 + 1] - mnew);
                accS[nf][half * 2] = p0;
                accS[nf][half * 2 + 1] = p1;
                ps += p0 + p1;
            }
            ps += __shfl_xor_sync(0xffffffffu, ps, 1);
            ps += __shfl_xor_sync(0xffffffffu, ps, 2);
            l[half] = l[half] * corr + ps;
#pragma unroll
            for (int nf = 0; nf < 8; nf++) {
                accO[nf][half * 2] *= corr;
                accO[nf][half * 2 + 1] *= corr;
            }
        }

#pragma unroll
        for (int ks2 = 0; ks2 < 8; ks2++) {
            uint32_t pah[4], pal[4];
            split2(accS[2 * ks2][0], accS[2 * ks2][1], pah[0], pal[0]);
            split2(accS[2 * ks2][2], accS[2 * ks2][3], pah[1], pal[1]);
            split2(accS[2 * ks2 + 1][0], accS[2 * ks2 + 1][1], pah[2], pal[2]);
            split2(accS[2 * ks2 + 1][2], accS[2 * ks2 + 1][3], pah[3], pal[3]);
            const uint32_t sub = (ks2 >> 2) * 8192;
            const uint32_t kb2 = (ks2 & 3) * 32 + kbl;
            uint32_t vh[4][4], vl[4][4];
#pragma unroll
            for (int np = 0; np < 4; np++) {
                const uint32_t voff = sub + SW128((uint32_t)((np * 16 + lrow) * 128) + kb2);
                ldsm4(vh[np], smV + voff);
                ldsm4(vl[np], smV + 16384 + voff);
            }
            // pass 1: p_h x v_h
#pragma unroll
            for (int np = 0; np < 4; np++)
#pragma unroll
                for (int sel = 0; sel < 2; sel++)
                    mma16816(accO[np * 2 + sel], pah, vh[np][sel], vh[np][sel + 2]);
            // pass 2: p_h x v_l
#pragma unroll
            for (int np = 0; np < 4; np++)
#pragma unroll
                for (int sel = 0; sel < 2; sel++)
                    mma16816(accO[np * 2 + sel], pah, vl[np][sel], vl[np][sel + 2]);
            // pass 3: p_l x v_h
#pragma unroll
            for (int np = 0; np < 4; np++)
#pragma unroll
                for (int sel = 0; sel < 2; sel++)
                    mma16816(accO[np * 2 + sel], pal, vh[np][sel], vh[np][sel + 2]);
        }
    }

    if ((lane & 3) == 0) {
        g_am[b][chunk][it][m0 + rr] = m[0];
        g_am[b][chunk][it][m0 + 8 + rr] = m[1];
        g_al[b][chunk][it][m0 + rr] = l[0];
        g_al[b][chunk][it][m0 + 8 + rr] = l[1];
    }
    float* aO = g_aO[b][chunk][it];
#pragma unroll
    for (int nf = 0; nf < 8; nf++) {
        const int gc = nf * 8 + cc;
        *(float2*)(aO + (m0 + rr) * 64 + gc) = make_float2(accO[nf][0], accO[nf][1]);
        *(float2*)(aO + (m0 + 8 + rr) * 64 + gc) = make_float2(accO[nf][2], accO[nf][3]);
    }
}

// ---------------------------------------------------------------------------
// K5: combine split-KV partials.  grid (16 it, 4 b), 256 thr.
// ---------------------------------------------------------------------------
__global__ void k_comb(float* __restrict__ out) {
    const int it = blockIdx.x, b = blockIdx.y;
    const int nch = it / 2 + 1;
    const int tid = threadIdx.x;
    const int r = tid >> 1;
    const int c0 = (tid & 1) * 32;

    float M = -1e30f;
#pragma unroll
    for (int c = 0; c < 8; c++)
        if (c < nch) M = fmaxf(M, g_am[b][c][it][r]);

    float w[8];
    float lt = 0.f;
#pragma unroll
    for (int c = 0; c < 8; c++) {
        w[c] = 0.f;
        if (c < nch) {
            w[c] = __expf(g_am[b][c][it][r] - M);
            lt += g_al[b][c][it][r] * w[c];
        }
    }
    const float inv = 1.f / lt;

    float* dst = out + ((size_t)b * SS + it * 128 + r) * DHE + c0;
#pragma unroll
    for (int j4 = 0; j4 < 8; j4++) {
        float4 acc = make_float4(0.f, 0.f, 0.f, 0.f);
#pragma unroll
        for (int c = 0; c < 8; c++)
            if (c < nch) {
                float4 v = *(const float4*)&g_aO[b][c][it][r * 64 + c0 + j4 * 4];
                acc.x = fmaf(v.x, w[c], acc.x);
                acc.y = fmaf(v.y, w[c], acc.y);
                acc.z = fmaf(v.z, w[c], acc.z);
                acc.w = fmaf(v.w, w[c], acc.w);
            }
        *(float4*)(dst + j4 * 4) =
            make_float4(acc.x * inv, acc.y * inv, acc.z * inv, acc.w * inv);
    }
}

// ---------------------------------------------------------------------------
extern "C" void kernel_launch(void* const* d_in, const int* in_sizes, int n_in,
                              void* d_out, int out_size) {
    const float* x   = (const float*)d_in[0];
    const float* wqu = (const float*)d_in[1];
    const float* wku = (const float*)d_in[2];
    const float* wvu = (const float*)d_in[3];
    const float* wqc = (const float*)d_in[4];
    const float* wkc = (const float*)d_in[5];
    const float* wvc = (const float*)d_in[6];
    float* out = (float*)d_out;

    k_cvt<<<2048, 256>>>(x, wqu, wku, wvu, wqc, wkc, wvc);

    const int proj_smem = 1024 + 2 * 49152;  // 99328 B
    cudaFuncSetAttribute(k_proj_mma, cudaFuncAttributeMaxDynamicSharedMemorySize, proj_smem);
    k_proj_mma<<<dim3(64, 6), 256, proj_smem>>>();

    k_vt<<<dim3(64, 4), 256>>>();

    const int pair_smem = 1024 + 65536;  // 66560 B
    cudaFuncSetAttribute(k_pair_mma, cudaFuncAttributeMaxDynamicSharedMemorySize, pair_smem);
    k_pair_mma<<<dim3(136, 4, 2), 256, pair_smem>>>();

    const int su_smem = 1024 + 2 * 65536;  // 132096 B
    cudaFuncSetAttribute(k_su_mma, cudaFuncAttributeMaxDynamicSharedMemorySize, su_smem);
    k_su_mma<<<dim3(272, 1, 4), 256, su_smem>>>();

    const int attn_smem = 1024 + 6 * 16384;  // 99328 B
    cudaFuncSetAttribute(k_attn_mma, cudaFuncAttributeMaxDynamicSharedMemorySize, attn_smem);
    k_attn_mma<<<dim3(16, 8, 4), 256, attn_smem>>>();

    k_comb<<<dim3(16, 4), 256>>>(out);
}

// round 15
// speedup vs baseline: 1.2453x; 1.2346x over previous
#include <cuda_runtime.h>
#include <cuda_fp16.h>
#include <cstdint>

#define BB 4
#define SS 2048
#define DD 1024
#define DHE 64
#define SCALE 0.125f

// ---------------- scratch (device globals) ----------------
static __device__ float g_P[6][BB * SS * DHE];           // only [5]=Vc used (f32)
static __device__ __half g_Ph[5][BB * SS * DHE];         // f16 of Qu,Ku,Vu,Qc,Kc
static __device__ __half g_Pl[5][BB * SS * DHE];         // lo (only heads 0,3 used)
static __device__ __half g_Vtf[(size_t)BB * DHE * SS];   // Vc^T [b][d][s] f16
static __device__ __half g_xh[(size_t)BB * SS * DD];
static __device__ __half g_xl[(size_t)BB * SS * DD];
static __device__ __half g_wf[6][DHE * DD];              // [head][n][k] f16
static __device__ __half g_t1h[(size_t)BB * SS * SS];
static __device__ __half g_t1l[(size_t)BB * SS * SS];
static __device__ __half g_sgh[(size_t)BB * SS * SS];    // sigmoid gate, single f16
static __device__ float g_suA[(size_t)BB * SS * SS];
static __device__ float g_suB[(size_t)BB * SS * SS];
// split-KV partials: 8 chunks (2 k-tiles of 128 each), 16 i-tiles of 128 rows
static __device__ float g_am[BB][8][16][128];
static __device__ float g_al[BB][8][16][128];
static __device__ float g_aO[BB][8][16][128 * 64];

// ---------------- helpers (compute_103-safe) ----------------
__device__ __forceinline__ uint32_t smem_to_u32(const void* p) {
    uint32_t a;
    asm("{ .reg .u64 t; cvta.to.shared.u64 t, %1; cvt.u32.u64 %0, t; }" : "=r"(a) : "l"(p));
    return a;
}
#define SW128(o) ((o) ^ (((o) >> 3) & 0x70))

__device__ __forceinline__ void ldsm4(uint32_t* r, uint32_t addr) {
    asm volatile("ldmatrix.sync.aligned.m8n8.x4.shared.b16 {%0,%1,%2,%3}, [%4];"
        : "=r"(r[0]), "=r"(r[1]), "=r"(r[2]), "=r"(r[3]) : "r"(addr));
}
__device__ __forceinline__ void mma16816(float* c, const uint32_t* a,
                                         uint32_t b0, uint32_t b1) {
    asm volatile("mma.sync.aligned.m16n8k16.row.col.f32.f16.f16.f32 "
        "{%0,%1,%2,%3}, {%4,%5,%6,%7}, {%8,%9}, {%0,%1,%2,%3};"
        : "+f"(c[0]), "+f"(c[1]), "+f"(c[2]), "+f"(c[3])
        : "r"(a[0]), "r"(a[1]), "r"(a[2]), "r"(a[3]), "r"(b0), "r"(b1));
}

__device__ __forceinline__ float fast_rcp(float y) {
    float r = __int_as_float(0x7EF127EAu - __float_as_int(y));
    r = r * fmaf(-y, r, 2.0f);
    r = r * fmaf(-y, r, 2.0f);
    r = r * fmaf(-y, r, 2.0f);
    return r;
}
__device__ __forceinline__ float fast_sigmoid(float x) {
    const float t = __expf(-fmaxf(x, -80.f));
    return fast_rcp(1.f + t);
}
__device__ __forceinline__ float fast_silu(float x) {
    return x * fast_sigmoid(x);
}
// split two floats into packed f16x2 hi / lo words
__device__ __forceinline__ void split2h(float v0, float v1, uint32_t& h, uint32_t& l) {
    const __half h0 = __float2half(v0), h1 = __float2half(v1);
    const __half l0 = __float2half(v0 - __half2float(h0));
    const __half l1 = __float2half(v1 - __half2float(h1));
    union { __half2 x; uint32_t u; } H, L;
    H.x = __halves2half2(h0, h1);
    L.x = __halves2half2(l0, l1);
    h = H.u; l = L.u;
}
__device__ __forceinline__ uint32_t pack2h(float v0, float v1) {
    union { __half2 x; uint32_t u; } H;
    H.x = __halves2half2(__float2half(v0), __float2half(v1));
    return H.u;
}

// ---------------------------------------------------------------------------
// K0: convert x (f16 hi/lo) AND weights (single f16), one launch
// ---------------------------------------------------------------------------
__global__ void k_cvt(const float* __restrict__ x,
                      const float* __restrict__ w0, const float* __restrict__ w1,
                      const float* __restrict__ w2, const float* __restrict__ w3,
                      const float* __restrict__ w4, const float* __restrict__ w5) {
    const size_t n_x = (size_t)BB * SS * DD;
    const size_t n_w = 6 * DD * DHE;
    const size_t n = n_x + n_w;
    for (size_t i = (size_t)blockIdx.x * blockDim.x + threadIdx.x; i < n;
         i += (size_t)gridDim.x * blockDim.x) {
        if (i < n_x) {
            const float v = x[i];
            const __half h = __float2half(v);
            g_xh[i] = h;
            g_xl[i] = __float2half(v - __half2float(h));
        } else {
            const int j = (int)(i - n_x);
            const int head = j >> 16;
            const int rem = j & 65535;
            const int k = rem >> 6, nn = rem & 63;
            const float* w = head == 0 ? w0 : head == 1 ? w1 : head == 2 ? w2
                           : head == 3 ? w3 : head == 4 ? w4 : w5;
            g_wf[head][nn * DD + k] = __float2half(w[k * DHE + nn]);
        }
    }
}

// ---------------------------------------------------------------------------
// K1: projections via mma.sync f16 A-split (2 products).  out[h] = x @ w[h].
// Stage: Ah 16K | Al 16K | Bf 8K = 40960 B.
// ---------------------------------------------------------------------------
__global__ void __launch_bounds__(256) k_proj_mma() {
    extern __shared__ char smem[];
    const uint32_t tiles = (smem_to_u32(smem) + 1023u) & ~1023u;
    const int row0 = blockIdx.x * 128, head = blockIdx.y;

    const int tid = threadIdx.x;
    const int wid = tid >> 5, lane = tid & 31;
    const int wm = wid & 3, wn = wid >> 2;
    const int lrow = lane & 15;
    const uint32_t kbl = (lane >> 4) * 16;

#define PJ_LOAD(stage, ch) do { \
    const uint32_t _st = tiles + (stage) * 40960; \
    _Pragma("unroll") \
    for (int q = 0; q < 4; q++) { \
        const int r = (tid >> 3) + q * 32; \
        const int c16 = tid & 7; \
        const uint32_t so = SW128((uint32_t)(r * 128 + c16 * 16)); \
        const size_t go = (size_t)(row0 + r) * DD + (ch) + c16 * 8; \
        asm volatile("cp.async.cg.shared.global [%0], [%1], 16;" :: "r"(_st + so), "l"(g_xh + go)); \
        asm volatile("cp.async.cg.shared.global [%0], [%1], 16;" :: "r"(_st + 16384 + so), "l"(g_xl + go)); \
    } \
    _Pragma("unroll") \
    for (int q = 0; q < 2; q++) { \
        const int r = (tid >> 3) + q * 32; \
        const int c16 = tid & 7; \
        const uint32_t so = SW128((uint32_t)(r * 128 + c16 * 16)); \
        const size_t go = (size_t)r * DD + (ch) + c16 * 8; \
        asm volatile("cp.async.cg.shared.global [%0], [%1], 16;" :: "r"(_st + 32768 + so), "l"(g_wf[head] + go)); \
    } \
    asm volatile("cp.async.commit_group;"); \
} while (0)

    float acc[2][4][4];
#pragma unroll
    for (int mf = 0; mf < 2; mf++)
#pragma unroll
        for (int nf = 0; nf < 4; nf++)
#pragma unroll
            for (int q = 0; q < 4; q++) acc[mf][nf][q] = 0.f;

    PJ_LOAD(0, 0);

    for (int c = 0; c < DD / 64; c++) {
        const int s = c & 1;
        if (c + 1 < DD / 64) {
            PJ_LOAD(s ^ 1, (c + 1) * 64);
            asm volatile("cp.async.wait_group 1;");
        } else {
            asm volatile("cp.async.wait_group 0;");
        }
        __syncthreads();

        const uint32_t stAh = tiles + s * 40960;
        const uint32_t stAl = stAh + 16384;
        const uint32_t stBf = stAh + 32768;

#pragma unroll
        for (int ks = 0; ks < 4; ks++) {
            const uint32_t kb = ks * 32 + kbl;
            uint32_t ah[2][4], al[2][4], bh[2][4];
#pragma unroll
            for (int mf = 0; mf < 2; mf++) {
                const uint32_t off = SW128((uint32_t)((wm * 32 + mf * 16 + lrow) * 128) + kb);
                ldsm4(ah[mf], stAh + off);
                ldsm4(al[mf], stAl + off);
            }
#pragma unroll
            for (int np = 0; np < 2; np++) {
                const uint32_t off = SW128((uint32_t)((wn * 32 + np * 16 + lrow) * 128) + kb);
                ldsm4(bh[np], stBf + off);
            }
            // pass 1: ah x b
#pragma unroll
            for (int mf = 0; mf < 2; mf++)
#pragma unroll
                for (int nf = 0; nf < 4; nf++) {
                    const int np = nf >> 1, sel = nf & 1;
                    mma16816(acc[mf][nf], ah[mf], bh[np][sel], bh[np][sel + 2]);
                }
            // pass 2: al x b
#pragma unroll
            for (int mf = 0; mf < 2; mf++)
#pragma unroll
                for (int nf = 0; nf < 4; nf++) {
                    const int np = nf >> 1, sel = nf & 1;
                    mma16816(acc[mf][nf], al[mf], bh[np][sel], bh[np][sel + 2]);
                }
        }
        __syncthreads();
    }
#undef PJ_LOAD

    const int rr = lane >> 2, cc = (lane & 3) * 2;
    if (head == 5) {
        float* C = g_P[5];
#pragma unroll
        for (int mf = 0; mf < 2; mf++) {
            const int gr = row0 + wm * 32 + mf * 16 + rr;
#pragma unroll
            for (int nf = 0; nf < 4; nf++) {
                const int gc = wn * 32 + nf * 8 + cc;
                *(float2*)(C + (size_t)gr * DHE + gc) = make_float2(acc[mf][nf][0], acc[mf][nf][1]);
                *(float2*)(C + (size_t)(gr + 8) * DHE + gc) = make_float2(acc[mf][nf][2], acc[mf][nf][3]);
            }
        }
    } else {
        const bool wantLo = (head == 0) || (head == 3);  // A-side operands (Qu, Qc)
        __half* Hh = g_Ph[head];
        __half* Hl = g_Pl[head];
#pragma unroll
        for (int mf = 0; mf < 2; mf++) {
            const int gr = row0 + wm * 32 + mf * 16 + rr;
#pragma unroll
            for (int nf = 0; nf < 4; nf++) {
                const int gc = wn * 32 + nf * 8 + cc;
                uint32_t h0, l0, h1, l1;
                split2h(acc[mf][nf][0], acc[mf][nf][1], h0, l0);
                split2h(acc[mf][nf][2], acc[mf][nf][3], h1, l1);
                *(uint32_t*)(Hh + (size_t)gr * DHE + gc) = h0;
                *(uint32_t*)(Hh + (size_t)(gr + 8) * DHE + gc) = h1;
                if (wantLo) {
                    *(uint32_t*)(Hl + (size_t)gr * DHE + gc) = l0;
                    *(uint32_t*)(Hl + (size_t)(gr + 8) * DHE + gc) = l1;
                }
            }
        }
    }
}

// ---------------------------------------------------------------------------
// K1b: transpose Vc -> [b][d][s] single f16.  grid (64 s-tiles of 32, 4 b).
// ---------------------------------------------------------------------------
__global__ void k_vt() {
    __shared__ float ts[32][65];
    const int s0 = blockIdx.x * 32, b = blockIdx.y;
    const int tid = threadIdx.x;
    for (int t = tid; t < 2048; t += 256) {
        const int r = t >> 6, c = t & 63;
        ts[r][c] = g_P[5][((size_t)b * SS + s0 + r) * DHE + c];
    }
    __syncthreads();
    for (int t = tid; t < 2048; t += 256) {
        const int d = t >> 5, sc = t & 31;
        g_Vtf[((size_t)b * DHE + d) * SS + s0 + sc] = __float2half(ts[sc][d]);
    }
}

// ---------------------------------------------------------------------------
// K2: term1 / sigmoid gate via mma.sync f16 A-split (2 products), 128x128.
// Tiles: Ah | Al | Bf = 49152 B.  grid (136 tri-pairs, 4 b, 2 modes), 256 thr.
// ---------------------------------------------------------------------------
__global__ void __launch_bounds__(256) k_pair_mma() {
    extern __shared__ char smem[];
    const uint32_t tiles = (smem_to_u32(smem) + 1023u) & ~1023u;

    const int mode = blockIdx.z, b = blockIdx.y;
    int pp = blockIdx.x;
    int d = 15;
    while (pp >= 16 - d) { pp -= 16 - d; d--; }
    const int rt = (mode == 0) ? (pp + d) : pp;
    const int ct = (mode == 0) ? pp : (pp + d);
    const int i0 = rt * 128, j0 = ct * 128;
    const int hA = (mode == 0) ? 3 : 0;   // Qc | Qu (A-split: hi+lo)
    const int hB = (mode == 0) ? 2 : 1;   // Vu | Ku (single)

    const int tid = threadIdx.x;
    const int wid = tid >> 5, lane = tid & 31;

    {
        const int ltile = tid >> 6;       // 0..3; group 3 idle
        const int llane = tid & 63;
        const int rl = llane >> 3, c16 = llane & 7;
        if (ltile < 3) {
            const __half* src =
                (ltile == 0) ? g_Ph[hA] + ((size_t)b * SS + i0) * DHE :
                (ltile == 1) ? g_Pl[hA] + ((size_t)b * SS + i0) * DHE :
                               g_Ph[hB] + ((size_t)b * SS + j0) * DHE;
            const __half* g = src + (size_t)rl * DHE + c16 * 8;
            const uint32_t tsm = tiles + ltile * 16384;
#pragma unroll
            for (int q = 0; q < 16; q++) {
                const uint32_t so = SW128((uint32_t)((q * 8 + rl) * 128 + c16 * 16));
                asm volatile("cp.async.cg.shared.global [%0], [%1], 16;"
                    :: "r"(tsm + so), "l"(g + (size_t)q * 8 * DHE));
            }
        }
        asm volatile("cp.async.commit_group;");
        asm volatile("cp.async.wait_group 0;");
    }
    __syncthreads();

    float acc[2][8][4];
#pragma unroll
    for (int mf = 0; mf < 2; mf++)
#pragma unroll
        for (int nf = 0; nf < 8; nf++)
#pragma unroll
            for (int q = 0; q < 4; q++) acc[mf][nf][q] = 0.f;

    const int wm = wid >> 1, wn = wid & 1;
    const int lrow = lane & 15;
    const uint32_t kbl = (lane >> 4) * 16;
    const uint32_t stAh = tiles, stAl = tiles + 16384, stBf = tiles + 32768;

#pragma unroll
    for (int ks = 0; ks < 4; ks++) {
        const uint32_t kb = ks * 32 + kbl;
        uint32_t ah[2][4], al[2][4], bh[4][4];
#pragma unroll
        for (int mf = 0; mf < 2; mf++) {
            const uint32_t off = SW128((uint32_t)((wm * 32 + mf * 16 + lrow) * 128) + kb);
            ldsm4(ah[mf], stAh + off);
            ldsm4(al[mf], stAl + off);
        }
#pragma unroll
        for (int np = 0; np < 4; np++) {
            const uint32_t off = SW128((uint32_t)((wn * 64 + np * 16 + lrow) * 128) + kb);
            ldsm4(bh[np], stBf + off);
        }
        // pass 1: ah x b
#pragma unroll
        for (int mf = 0; mf < 2; mf++)
#pragma unroll
            for (int nf = 0; nf < 8; nf++) {
                const int np = nf >> 1, sel = nf & 1;
                mma16816(acc[mf][nf], ah[mf], bh[np][sel], bh[np][sel + 2]);
            }
        // pass 2: al x b
#pragma unroll
        for (int mf = 0; mf < 2; mf++)
#pragma unroll
            for (int nf = 0; nf < 8; nf++) {
                const int np = nf >> 1, sel = nf & 1;
                mma16816(acc[mf][nf], al[mf], bh[np][sel], bh[np][sel + 2]);
            }
    }

    const size_t boff = (size_t)b * SS * SS;
    const int rr = lane >> 2, cc = (lane & 3) * 2;
    if (mode == 0) {
        __half* outh = g_t1h + boff;
        __half* outl = g_t1l + boff;
#pragma unroll
        for (int mf = 0; mf < 2; mf++)
#pragma unroll
            for (int half = 0; half < 2; half++) {
                const int gi = i0 + wm * 32 + mf * 16 + half * 8 + rr;
#pragma unroll
                for (int nf = 0; nf < 8; nf++) {
                    const int gc = j0 + wn * 64 + nf * 8 + cc;
                    float v0 = acc[mf][nf][half * 2 + 0] * SCALE;
                    float v1 = acc[mf][nf][half * 2 + 1] * SCALE;
                    v0 = (gc <= gi) ? v0 : 0.f;
                    v1 = (gc + 1 <= gi) ? v1 : 0.f;
                    uint32_t h, l;
                    split2h(v0, v1, h, l);
                    *(uint32_t*)(outh + (size_t)gi * SS + gc) = h;
                    *(uint32_t*)(outl + (size_t)gi * SS + gc) = l;
                }
            }
    } else {
        __half* outh = g_sgh + boff;
#pragma unroll
        for (int mf = 0; mf < 2; mf++)
#pragma unroll
            for (int half = 0; half < 2; half++) {
                const int gi = i0 + wm * 32 + mf * 16 + half * 8 + rr;
#pragma unroll
                for (int nf = 0; nf < 8; nf++) {
                    const int gc = j0 + wn * 64 + nf * 8 + cc;
                    float v0 = acc[mf][nf][half * 2 + 0] * SCALE;
                    float v1 = acc[mf][nf][half * 2 + 1] * SCALE;
                    v0 = (gc > gi) ? fast_sigmoid(v0) : 0.f;
                    v1 = (gc + 1 > gi) ? fast_sigmoid(v1) : 0.f;
                    *(uint32_t*)(outh + (size_t)gi * SS + gc) = pack2h(v0, v1);
                }
            }
    }
}

// ---------------------------------------------------------------------------
// K3: S_u via mma.sync f16 A-split (2 products), j-SPLIT, 2-stage pipeline.
// Chunk: t1h 16K | t1l 16K | sg 16K = 49152 B/stage.
// grid (272, 1, 4 b), 256 thr, 99328 B smem.
// ---------------------------------------------------------------------------
__global__ void __launch_bounds__(256) k_su_mma() {
    extern __shared__ char smem[];
    const uint32_t tiles = (smem_to_u32(smem) + 1023u) & ~1023u;

    const int b = blockIdx.z;
    const int seg = blockIdx.x & 1;
    int pp = blockIdx.x >> 1;
    int d = 15;
    while (pp >= 16 - d) { pp -= 16 - d; d--; }
    const int kt = pp, it = pp + d;
    const int i0 = it * 128, k0 = kt * 128;

    int jbeg = k0, jend = (it + 1) * 128;
    const int mid = jbeg + ((jend - jbeg) >> 1);
    if (seg == 0) jend = mid; else jbeg = mid;
    const int nch = (jend - jbeg) >> 6;

    const int tid = threadIdx.x;
    const int wid = tid >> 5, lane = tid & 31;

    const int ltile = tid >> 6;   // 0..3; group 3 idle during loads
    const int llane = tid & 63;
    const int rl = llane >> 3;
    const int c16 = llane & 7;
    const size_t boff = (size_t)b * SS * SS;
    const __half* src =
        (ltile == 0) ? g_t1h + boff + (size_t)i0 * SS :
        (ltile == 1) ? g_t1l + boff + (size_t)i0 * SS :
                       g_sgh + boff + (size_t)k0 * SS;
    const __half* gbase = src + (size_t)rl * SS + c16 * 8;
    const uint32_t tsm = tiles + ltile * 16384;

#define SU_LOAD_CHUNK(stage, j0v) do { \
    if (ltile < 3) { \
        const __half* _g = gbase + (j0v); \
        const uint32_t _base = tsm + (stage) * 49152; \
        _Pragma("unroll") \
        for (int q = 0; q < 16; q++) { \
            uint32_t so = (uint32_t)((q * 8 + rl) * 128 + c16 * 16); \
            uint32_t sa = _base + SW128(so); \
            asm volatile("cp.async.cg.shared.global [%0], [%1], 16;" :: "r"(sa), "l"(_g + (size_t)q * 8 * SS)); \
        } \
    } \
    asm volatile("cp.async.commit_group;"); \
} while (0)

    float acc[2][8][4];
#pragma unroll
    for (int mf = 0; mf < 2; mf++)
#pragma unroll
        for (int nf = 0; nf < 8; nf++)
#pragma unroll
            for (int q = 0; q < 4; q++) acc[mf][nf][q] = 0.f;

    const int wm = wid >> 1, wn = wid & 1;
    const int lrow = lane & 15;
    const uint32_t kbl = (lane >> 4) * 16;

    SU_LOAD_CHUNK(0, jbeg);

    for (int i = 0; i < nch; i++) {
        const int s = i & 1;
        if (i + 1 < nch) {
            SU_LOAD_CHUNK(s ^ 1, jbeg + (i + 1) * 64);
            asm volatile("cp.async.wait_group 1;");
        } else {
            asm volatile("cp.async.wait_group 0;");
        }
        __syncthreads();

        const uint32_t stAh = tiles + s * 49152;
        const uint32_t stAl = stAh + 16384;
        const uint32_t stBf = stAh + 32768;

#pragma unroll
        for (int ks = 0; ks < 4; ks++) {
            const uint32_t kb = ks * 32 + kbl;
            uint32_t ah[2][4], al[2][4], bh[4][4];
#pragma unroll
            for (int mf = 0; mf < 2; mf++) {
                const uint32_t off = SW128((uint32_t)((wm * 32 + mf * 16 + lrow) * 128) + kb);
                ldsm4(ah[mf], stAh + off);
                ldsm4(al[mf], stAl + off);
            }
#pragma unroll
            for (int np = 0; np < 4; np++) {
                const uint32_t off = SW128((uint32_t)((wn * 64 + np * 16 + lrow) * 128) + kb);
                ldsm4(bh[np], stBf + off);
            }
            // pass 1: ah x b
#pragma unroll
            for (int mf = 0; mf < 2; mf++)
#pragma unroll
                for (int nf = 0; nf < 8; nf++) {
                    const int np = nf >> 1, sel = nf & 1;
                    mma16816(acc[mf][nf], ah[mf], bh[np][sel], bh[np][sel + 2]);
                }
            // pass 2: al x b
#pragma unroll
            for (int mf = 0; mf < 2; mf++)
#pragma unroll
                for (int nf = 0; nf < 8; nf++) {
                    const int np = nf >> 1, sel = nf & 1;
                    mma16816(acc[mf][nf], al[mf], bh[np][sel], bh[np][sel + 2]);
                }
        }
        __syncthreads();
    }
#undef SU_LOAD_CHUNK

    float* C = (seg ? g_suB : g_suA) + boff;
    const int rr = lane >> 2, cc = (lane & 3) * 2;
#pragma unroll
    for (int mf = 0; mf < 2; mf++) {
        const int gr = i0 + wm * 32 + mf * 16 + rr;
#pragma unroll
        for (int nf = 0; nf < 8; nf++) {
            const int gc = k0 + wn * 64 + nf * 8 + cc;
            *(float2*)(C + (size_t)gr * SS + gc) = make_float2(acc[mf][nf][0], acc[mf][nf][1]);
            *(float2*)(C + (size_t)(gr + 8) * SS + gc) = make_float2(acc[mf][nf][2], acc[mf][nf][3]);
        }
    }
}

// ---------------------------------------------------------------------------
// K4: flash attention partial via mma.sync f16 (2 products), 2 k-tiles/chunk.
// smem: Qh 16K | Ql 16K | Kf 16K | Vf 16K = 66560 B.
// grid (16 it, 8 chunk, 4 b), 256 thr.
// ---------------------------------------------------------------------------
__global__ void __launch_bounds__(256) k_attn_mma() {
    const int it = blockIdx.x, chunk = blockIdx.y, b = blockIdx.z;
    if (chunk * 2 > it) return;
    const int kt_beg = chunk * 2;
    const int kt_end = min(kt_beg + 2, it + 1);
    const int i0 = it * 128;

    extern __shared__ char smem[];
    const uint32_t sb = (smem_to_u32(smem) + 1023u) & ~1023u;
    const uint32_t smQh = sb;
    const uint32_t smQl = sb + 16384;
    const uint32_t smK = sb + 32768;
    const uint32_t smV = sb + 49152;

    const int tid = threadIdx.x;
    const int wid = tid >> 5, lane = tid & 31;
    const int m0 = wid * 16;
    const int lrow = lane & 15;
    const uint32_t kbl = (lane >> 4) * 16;
    const int rr = lane >> 2, cc = (lane & 3) * 2;

    // load Q (hi+lo) once
    for (int t = tid; t < 2048; t += 256) {
        const int half = t >> 10, r = (t >> 3) & 127, c16 = t & 7;
        const __half* src = (half ? g_Pl[3] : g_Ph[3])
            + ((size_t)b * SS + i0 + r) * DHE + c16 * 8;
        const uint32_t dst = (half ? smQl : smQh) + SW128((uint32_t)(r * 128 + c16 * 16));
        asm volatile("cp.async.cg.shared.global [%0], [%1], 16;" :: "r"(dst), "l"(src));
    }
    asm volatile("cp.async.commit_group;");

    const float* SuA = g_suA + (size_t)b * SS * SS;
    const float* SuB = g_suB + (size_t)b * SS * SS;

    float m[2] = {-1e30f, -1e30f}, l[2] = {0.f, 0.f};
    float accO[8][4];
#pragma unroll
    for (int nf = 0; nf < 8; nf++)
#pragma unroll
        for (int q = 0; q < 4; q++) accO[nf][q] = 0.f;

    for (int kt = kt_beg; kt < kt_end; kt++) {
        const int k0t = kt * 128;
        __syncthreads();
        for (int t = tid; t < 1024; t += 256) {
            const int r = t >> 3, c16 = t & 7;
            const __half* src = g_Ph[4] + ((size_t)b * SS + k0t + r) * DHE + c16 * 8;
            asm volatile("cp.async.cg.shared.global [%0], [%1], 16;"
                :: "r"(smK + SW128((uint32_t)(r * 128 + c16 * 16))), "l"(src));
        }
        for (int t = tid; t < 1024; t += 256) {
            const int rw = t >> 3, c16 = t & 7;
            const int dd = rw & 63, sub = rw >> 6;
            const __half* src = g_Vtf + ((size_t)b * DHE + dd) * SS + k0t + sub * 64 + c16 * 8;
            const uint32_t dst = smV + sub * 8192 + SW128((uint32_t)(dd * 128 + c16 * 16));
            asm volatile("cp.async.cg.shared.global [%0], [%1], 16;" :: "r"(dst), "l"(src));
        }
        asm volatile("cp.async.commit_group;");
        asm volatile("cp.async.wait_group 0;");
        __syncthreads();

        // ---- Sc = Q K^T (2 products) ----
        float accS[16][4];
#pragma unroll
        for (int nf = 0; nf < 16; nf++)
#pragma unroll
            for (int q = 0; q < 4; q++) accS[nf][q] = 0.f;

#pragma unroll
        for (int ks = 0; ks < 4; ks++) {
            const uint32_t kb = ks * 32 + kbl;
            uint32_t ah[4], al[4];
            const uint32_t aoff = SW128((uint32_t)((m0 + lrow) * 128) + kb);
            ldsm4(ah, smQh + aoff);
            ldsm4(al, smQl + aoff);
#pragma unroll
            for (int g = 0; g < 2; g++) {
                uint32_t bh[4][4];
#pragma unroll
                for (int n4 = 0; n4 < 4; n4++) {
                    const int np = g * 4 + n4;
                    const uint32_t boffs = SW128((uint32_t)((np * 16 + lrow) * 128) + kb);
                    ldsm4(bh[n4], smK + boffs);
                }
#pragma unroll
                for (int n4 = 0; n4 < 4; n4++)
#pragma unroll
                    for (int sel = 0; sel < 2; sel++)
                        mma16816(accS[(g * 4 + n4) * 2 + sel], ah, bh[n4][sel], bh[n4][sel + 2]);
#pragma unroll
                for (int n4 = 0; n4 < 4; n4++)
#pragma unroll
                    for (int sel = 0; sel < 2; sel++)
                        mma16816(accS[(g * 4 + n4) * 2 + sel], al, bh[n4][sel], bh[n4][sel + 2]);
            }
        }

        // ---- logits ----
        const bool diag = (kt == it);
#pragma unroll
        for (int nf = 0; nf < 16; nf++) {
            const int gk = k0t + nf * 8 + cc;
#pragma unroll
            for (int half = 0; half < 2; half++) {
                const int gi = i0 + m0 + half * 8 + rr;
                const float2 a2 = *(const float2*)(SuA + (size_t)gi * SS + gk);
                const float2 b2 = *(const float2*)(SuB + (size_t)gi * SS + gk);
                float v0 = accS[nf][half * 2 + 0] * SCALE - fast_silu(a2.x + b2.x);
                float v1 = accS[nf][half * 2 + 1] * SCALE - fast_silu(a2.y + b2.y);
                if (diag) {
                    if (gk > gi) v0 = -1e30f;
                    if (gk + 1 > gi) v1 = -1e30f;
                }
                accS[nf][half * 2 + 0] = v0;
                accS[nf][half * 2 + 1] = v1;
            }
        }

        // ---- online softmax ----
#pragma unroll
        for (int half = 0; half < 2; half++) {
            float mx = -1e30f;
#pragma unroll
            for (int nf = 0; nf < 16; nf++)
                mx = fmaxf(mx, fmaxf(accS[nf][half * 2], accS[nf][half * 2 + 1]));
            mx = fmaxf(mx, __shfl_xor_sync(0xffffffffu, mx, 1));
            mx = fmaxf(mx, __shfl_xor_sync(0xffffffffu, mx, 2));
            const float mnew = fmaxf(m[half], mx);
            const float corr = __expf(m[half] - mnew);
            m[half] = mnew;
            float ps = 0.f;
#pragma unroll
            for (int nf = 0; nf < 16; nf++) {
                const float p0 = __expf(accS[nf][half * 2] - mnew);
                const float p1 = __expf(accS[nf][half * 2 + 1] - mnew);
                accS[nf][half * 2] = p0;
                accS[nf][half * 2 + 1] = p1;
                ps += p0 + p1;
            }
            ps += __shfl_xor_sync(0xffffffffu, ps, 1);
            ps += __shfl_xor_sync(0xffffffffu, ps, 2);
            l[half] = l[half] * corr + ps;
#pragma unroll
            for (int nf = 0; nf < 8; nf++) {
                accO[nf][half * 2] *= corr;
                accO[nf][half * 2 + 1] *= corr;
            }
        }

        // ---- O += P @ V (P split hi/lo, V single: 2 products) ----
#pragma unroll
        for (int ks2 = 0; ks2 < 8; ks2++) {
            uint32_t pah[4], pal[4];
            split2h(accS[2 * ks2][0], accS[2 * ks2][1], pah[0], pal[0]);
            split2h(accS[2 * ks2][2], accS[2 * ks2][3], pah[1], pal[1]);
            split2h(accS[2 * ks2 + 1][0], accS[2 * ks2 + 1][1], pah[2], pal[2]);
            split2h(accS[2 * ks2 + 1][2], accS[2 * ks2 + 1][3], pah[3], pal[3]);
            const uint32_t sub = (ks2 >> 2) * 8192;
            const uint32_t kb2 = (ks2 & 3) * 32 + kbl;
            uint32_t vh[4][4];
#pragma unroll
            for (int np = 0; np < 4; np++) {
                const uint32_t voff = sub + SW128((uint32_t)((np * 16 + lrow) * 128) + kb2);
                ldsm4(vh[np], smV + voff);
            }
#pragma unroll
            for (int np = 0; np < 4; np++)
#pragma unroll
                for (int sel = 0; sel < 2; sel++)
                    mma16816(accO[np * 2 + sel], pah, vh[np][sel], vh[np][sel + 2]);
#pragma unroll
            for (int np = 0; np < 4; np++)
#pragma unroll
                for (int sel = 0; sel < 2; sel++)
                    mma16816(accO[np * 2 + sel], pal, vh[np][sel], vh[np][sel + 2]);
        }
    }

    if ((lane & 3) == 0) {
        g_am[b][chunk][it][m0 + rr] = m[0];
        g_am[b][chunk][it][m0 + 8 + rr] = m[1];
        g_al[b][chunk][it][m0 + rr] = l[0];
        g_al[b][chunk][it][m0 + 8 + rr] = l[1];
    }
    float* aO = g_aO[b][chunk][it];
#pragma unroll
    for (int nf = 0; nf < 8; nf++) {
        const int gc = nf * 8 + cc;
        *(float2*)(aO + (m0 + rr) * 64 + gc) = make_float2(accO[nf][0], accO[nf][1]);
        *(float2*)(aO + (m0 + 8 + rr) * 64 + gc) = make_float2(accO[nf][2], accO[nf][3]);
    }
}

// ---------------------------------------------------------------------------
// K5: combine split-KV partials.  grid (16 it, 4 b), 256 thr.
// ---------------------------------------------------------------------------
__global__ void k_comb(float* __restrict__ out) {
    const int it = blockIdx.x, b = blockIdx.y;
    const int nch = it / 2 + 1;
    const int tid = threadIdx.x;
    const int r = tid >> 1;
    const int c0 = (tid & 1) * 32;

    float M = -1e30f;
#pragma unroll
    for (int c = 0; c < 8; c++)
        if (c < nch) M = fmaxf(M, g_am[b][c][it][r]);

    float w[8];
    float lt = 0.f;
#pragma unroll
    for (int c = 0; c < 8; c++) {
        w[c] = 0.f;
        if (c < nch) {
            w[c] = __expf(g_am[b][c][it][r] - M);
            lt += g_al[b][c][it][r] * w[c];
        }
    }
    const float inv = 1.f / lt;

    float* dst = out + ((size_t)b * SS + it * 128 + r) * DHE + c0;
#pragma unroll
    for (int j4 = 0; j4 < 8; j4++) {
        float4 acc = make_float4(0.f, 0.f, 0.f, 0.f);
#pragma unroll
        for (int c = 0; c < 8; c++)
            if (c < nch) {
                float4 v = *(const float4*)&g_aO[b][c][it][r * 64 + c0 + j4 * 4];
                acc.x = fmaf(v.x, w[c], acc.x);
                acc.y = fmaf(v.y, w[c], acc.y);
                acc.z = fmaf(v.z, w[c], acc.z);
                acc.w = fmaf(v.w, w[c], acc.w);
            }
        *(float4*)(dst + j4 * 4) =
            make_float4(acc.x * inv, acc.y * inv, acc.z * inv, acc.w * inv);
    }
}

// ---------------------------------------------------------------------------
extern "C" void kernel_launch(void* const* d_in, const int* in_sizes, int n_in,
                              void* d_out, int out_size) {
    const float* x   = (const float*)d_in[0];
    const float* wqu = (const float*)d_in[1];
    const float* wku = (const float*)d_in[2];
    const float* wvu = (const float*)d_in[3];
    const float* wqc = (const float*)d_in[4];
    const float* wkc = (const float*)d_in[5];
    const float* wvc = (const float*)d_in[6];
    float* out = (float*)d_out;

    k_cvt<<<2048, 256>>>(x, wqu, wku, wvu, wqc, wkc, wvc);

    const int proj_smem = 1024 + 2 * 40960;  // 82944 B
    cudaFuncSetAttribute(k_proj_mma, cudaFuncAttributeMaxDynamicSharedMemorySize, proj_smem);
    k_proj_mma<<<dim3(64, 6), 256, proj_smem>>>();

    k_vt<<<dim3(64, 4), 256>>>();

    const int pair_smem = 1024 + 3 * 16384;  // 50176 B
    cudaFuncSetAttribute(k_pair_mma, cudaFuncAttributeMaxDynamicSharedMemorySize, pair_smem);
    k_pair_mma<<<dim3(136, 4, 2), 256, pair_smem>>>();

    const int su_smem = 1024 + 2 * 49152;  // 99328 B
    cudaFuncSetAttribute(k_su_mma, cudaFuncAttributeMaxDynamicSharedMemorySize, su_smem);
    k_su_mma<<<dim3(272, 1, 4), 256, su_smem>>>();

    const int attn_smem = 1024 + 4 * 16384;  // 66560 B
    cudaFuncSetAttribute(k_attn_mma, cudaFuncAttributeMaxDynamicSharedMemorySize, attn_smem);
    k_attn_mma<<<dim3(16, 8, 4), 256, attn_smem>>>();

    k_comb<<<dim3(16, 4), 256>>>(out);
}

// round 16
// speedup vs baseline: 1.2644x; 1.0153x over previous
#include <cuda_runtime.h>
#include <cuda_fp16.h>
#include <cstdint>

#define BB 4
#define SS 2048
#define DD 1024
#define DHE 64
#define SCALE 0.125f

// ---------------- scratch (device globals) ----------------
static __device__ __half g_Ph[5][BB * SS * DHE];         // f16 of Qu,Ku,Vu,Qc,Kc
static __device__ __half g_Pl[5][BB * SS * DHE];         // lo (only heads 0,3 used)
static __device__ __half g_Vtf[(size_t)BB * DHE * SS];   // Vc^T [b][d][s] f16
static __device__ __half g_xh[(size_t)BB * SS * DD];
static __device__ __half g_xl[(size_t)BB * SS * DD];
static __device__ __half g_wf[6][DHE * DD];              // [head][n][k] f16
static __device__ __half g_t1h[(size_t)BB * SS * SS];
static __device__ __half g_t1l[(size_t)BB * SS * SS];
static __device__ __half g_sgh[(size_t)BB * SS * SS];    // sigmoid gate, single f16
static __device__ float g_suA[(size_t)BB * SS * SS];
static __device__ float g_suB[(size_t)BB * SS * SS];
// split-KV partials: 8 chunks (2 k-tiles of 128 each), 16 i-tiles of 128 rows
static __device__ float g_am[BB][8][16][128];
static __device__ float g_al[BB][8][16][128];
static __device__ float g_aO[BB][8][16][128 * 64];

// ---------------- helpers (compute_103-safe) ----------------
__device__ __forceinline__ uint32_t smem_to_u32(const void* p) {
    uint32_t a;
    asm("{ .reg .u64 t; cvta.to.shared.u64 t, %1; cvt.u32.u64 %0, t; }" : "=r"(a) : "l"(p));
    return a;
}
#define SW128(o) ((o) ^ (((o) >> 3) & 0x70))

__device__ __forceinline__ void ldsm4(uint32_t* r, uint32_t addr) {
    asm volatile("ldmatrix.sync.aligned.m8n8.x4.shared.b16 {%0,%1,%2,%3}, [%4];"
        : "=r"(r[0]), "=r"(r[1]), "=r"(r[2]), "=r"(r[3]) : "r"(addr));
}
__device__ __forceinline__ void mma16816(float* c, const uint32_t* a,
                                         uint32_t b0, uint32_t b1) {
    asm volatile("mma.sync.aligned.m16n8k16.row.col.f32.f16.f16.f32 "
        "{%0,%1,%2,%3}, {%4,%5,%6,%7}, {%8,%9}, {%0,%1,%2,%3};"
        : "+f"(c[0]), "+f"(c[1]), "+f"(c[2]), "+f"(c[3])
        : "r"(a[0]), "r"(a[1]), "r"(a[2]), "r"(a[3]), "r"(b0), "r"(b1));
}

__device__ __forceinline__ float fast_rcp(float y) {
    float r = __int_as_float(0x7EF127EAu - __float_as_int(y));
    r = r * fmaf(-y, r, 2.0f);
    r = r * fmaf(-y, r, 2.0f);
    r = r * fmaf(-y, r, 2.0f);
    return r;
}
__device__ __forceinline__ float fast_sigmoid(float x) {
    const float t = __expf(-fmaxf(x, -80.f));
    return fast_rcp(1.f + t);
}
__device__ __forceinline__ float fast_silu(float x) {
    return x * fast_sigmoid(x);
}
__device__ __forceinline__ void split2h(float v0, float v1, uint32_t& h, uint32_t& l) {
    const __half h0 = __float2half(v0), h1 = __float2half(v1);
    const __half l0 = __float2half(v0 - __half2float(h0));
    const __half l1 = __float2half(v1 - __half2float(h1));
    union { __half2 x; uint32_t u; } H, L;
    H.x = __halves2half2(h0, h1);
    L.x = __halves2half2(l0, l1);
    h = H.u; l = L.u;
}
__device__ __forceinline__ uint32_t pack2h(float v0, float v1) {
    union { __half2 x; uint32_t u; } H;
    H.x = __halves2half2(__float2half(v0), __float2half(v1));
    return H.u;
}

// ---------------------------------------------------------------------------
// K0: convert x (f16 hi/lo) AND weights (single f16), one launch
// ---------------------------------------------------------------------------
__global__ void k_cvt(const float* __restrict__ x,
                      const float* __restrict__ w0, const float* __restrict__ w1,
                      const float* __restrict__ w2, const float* __restrict__ w3,
                      const float* __restrict__ w4, const float* __restrict__ w5) {
    const size_t n_x = (size_t)BB * SS * DD;
    const size_t n_w = 6 * DD * DHE;
    const size_t n = n_x + n_w;
    for (size_t i = (size_t)blockIdx.x * blockDim.x + threadIdx.x; i < n;
         i += (size_t)gridDim.x * blockDim.x) {
        if (i < n_x) {
            const float v = x[i];
            const __half h = __float2half(v);
            g_xh[i] = h;
            g_xl[i] = __float2half(v - __half2float(h));
        } else {
            const int j = (int)(i - n_x);
            const int head = j >> 16;
            const int rem = j & 65535;
            const int k = rem >> 6, nn = rem & 63;
            const float* w = head == 0 ? w0 : head == 1 ? w1 : head == 2 ? w2
                           : head == 3 ? w3 : head == 4 ? w4 : w5;
            g_wf[head][nn * DD + k] = __float2half(w[k * DHE + nn]);
        }
    }
}

// ---------------------------------------------------------------------------
// K1: projections via mma.sync f16 A-split (2 products).  out[h] = x @ w[h].
// head 5 (Vc) writes g_Vtf transposed directly via smem staging (k_vt fused).
// ---------------------------------------------------------------------------
__global__ void __launch_bounds__(256) k_proj_mma() {
    extern __shared__ char smem[];
    const uint32_t tiles = (smem_to_u32(smem) + 1023u) & ~1023u;
    const int row0 = blockIdx.x * 128, head = blockIdx.y;

    const int tid = threadIdx.x;
    const int wid = tid >> 5, lane = tid & 31;
    const int wm = wid & 3, wn = wid >> 2;
    const int lrow = lane & 15;
    const uint32_t kbl = (lane >> 4) * 16;

#define PJ_LOAD(stage, ch) do { \
    const uint32_t _st = tiles + (stage) * 40960; \
    _Pragma("unroll") \
    for (int q = 0; q < 4; q++) { \
        const int r = (tid >> 3) + q * 32; \
        const int c16 = tid & 7; \
        const uint32_t so = SW128((uint32_t)(r * 128 + c16 * 16)); \
        const size_t go = (size_t)(row0 + r) * DD + (ch) + c16 * 8; \
        asm volatile("cp.async.cg.shared.global [%0], [%1], 16;" :: "r"(_st + so), "l"(g_xh + go)); \
        asm volatile("cp.async.cg.shared.global [%0], [%1], 16;" :: "r"(_st + 16384 + so), "l"(g_xl + go)); \
    } \
    _Pragma("unroll") \
    for (int q = 0; q < 2; q++) { \
        const int r = (tid >> 3) + q * 32; \
        const int c16 = tid & 7; \
        const uint32_t so = SW128((uint32_t)(r * 128 + c16 * 16)); \
        const size_t go = (size_t)r * DD + (ch) + c16 * 8; \
        asm volatile("cp.async.cg.shared.global [%0], [%1], 16;" :: "r"(_st + 32768 + so), "l"(g_wf[head] + go)); \
    } \
    asm volatile("cp.async.commit_group;"); \
} while (0)

    float acc[2][4][4];
#pragma unroll
    for (int mf = 0; mf < 2; mf++)
#pragma unroll
        for (int nf = 0; nf < 4; nf++)
#pragma unroll
            for (int q = 0; q < 4; q++) acc[mf][nf][q] = 0.f;

    PJ_LOAD(0, 0);

    for (int c = 0; c < DD / 64; c++) {
        const int s = c & 1;
        if (c + 1 < DD / 64) {
            PJ_LOAD(s ^ 1, (c + 1) * 64);
            asm volatile("cp.async.wait_group 1;");
        } else {
            asm volatile("cp.async.wait_group 0;");
        }
        __syncthreads();

        const uint32_t stAh = tiles + s * 40960;
        const uint32_t stAl = stAh + 16384;
        const uint32_t stBf = stAh + 32768;

#pragma unroll
        for (int ks = 0; ks < 4; ks++) {
            const uint32_t kb = ks * 32 + kbl;
            uint32_t ah[2][4], al[2][4], bh[2][4];
#pragma unroll
            for (int mf = 0; mf < 2; mf++) {
                const uint32_t off = SW128((uint32_t)((wm * 32 + mf * 16 + lrow) * 128) + kb);
                ldsm4(ah[mf], stAh + off);
                ldsm4(al[mf], stAl + off);
            }
#pragma unroll
            for (int np = 0; np < 2; np++) {
                const uint32_t off = SW128((uint32_t)((wn * 32 + np * 16 + lrow) * 128) + kb);
                ldsm4(bh[np], stBf + off);
            }
#pragma unroll
            for (int mf = 0; mf < 2; mf++)
#pragma unroll
                for (int nf = 0; nf < 4; nf++) {
                    const int np = nf >> 1, sel = nf & 1;
                    mma16816(acc[mf][nf], ah[mf], bh[np][sel], bh[np][sel + 2]);
                }
#pragma unroll
            for (int mf = 0; mf < 2; mf++)
#pragma unroll
                for (int nf = 0; nf < 4; nf++) {
                    const int np = nf >> 1, sel = nf & 1;
                    mma16816(acc[mf][nf], al[mf], bh[np][sel], bh[np][sel + 2]);
                }
        }
        __syncthreads();
    }
#undef PJ_LOAD

    const int rr = lane >> 2, cc = (lane & 3) * 2;
    if (head == 5) {
        // Vc: stage transposed f16 in smem, then coalesced store to g_Vtf.
        __half* sd = (__half*)smem;   // [64 d][136 stride]
        const int PADS = 136;
#pragma unroll
        for (int mf = 0; mf < 2; mf++) {
            const int row = wm * 32 + mf * 16 + rr;
#pragma unroll
            for (int nf = 0; nf < 4; nf++) {
                const int col = wn * 32 + nf * 8 + cc;
                sd[col * PADS + row]           = __float2half(acc[mf][nf][0]);
                sd[(col + 1) * PADS + row]     = __float2half(acc[mf][nf][1]);
                sd[col * PADS + row + 8]       = __float2half(acc[mf][nf][2]);
                sd[(col + 1) * PADS + row + 8] = __float2half(acc[mf][nf][3]);
            }
        }
        __syncthreads();
        const int b = row0 >> 11;            // row0 / SS
        const int s_base = row0 & (SS - 1);
        for (int t = tid; t < 64 * 8; t += 256) {
            const int dd = t >> 3, s16 = (t & 7) * 16;
            __half* dst = g_Vtf + ((size_t)b * DHE + dd) * SS + s_base + s16;
            const __half* srcp = sd + dd * PADS + s16;
#pragma unroll
            for (int q = 0; q < 2; q++)
                *(uint4*)(dst + q * 8) = *(const uint4*)(srcp + q * 8);
        }
    } else {
        const bool wantLo = (head == 0) || (head == 3);  // A-side operands (Qu, Qc)
        __half* Hh = g_Ph[head];
        __half* Hl = g_Pl[head];
#pragma unroll
        for (int mf = 0; mf < 2; mf++) {
            const int gr = row0 + wm * 32 + mf * 16 + rr;
#pragma unroll
            for (int nf = 0; nf < 4; nf++) {
                const int gc = wn * 32 + nf * 8 + cc;
                uint32_t h0, l0, h1, l1;
                split2h(acc[mf][nf][0], acc[mf][nf][1], h0, l0);
                split2h(acc[mf][nf][2], acc[mf][nf][3], h1, l1);
                *(uint32_t*)(Hh + (size_t)gr * DHE + gc) = h0;
                *(uint32_t*)(Hh + (size_t)(gr + 8) * DHE + gc) = h1;
                if (wantLo) {
                    *(uint32_t*)(Hl + (size_t)gr * DHE + gc) = l0;
                    *(uint32_t*)(Hl + (size_t)(gr + 8) * DHE + gc) = l1;
                }
            }
        }
    }
}

// ---------------------------------------------------------------------------
// K2: term1 / sigmoid gate via mma.sync f16 A-split, 128x128 tiles.
// TWO jobs per block with 2-stage cp.async prefetch (hide L2 latency).
// grid (68, 4 b, 2 modes), 256 thr, 99328 B smem.
// ---------------------------------------------------------------------------
__global__ void __launch_bounds__(256) k_pair_mma() {
    extern __shared__ char smem[];
    const uint32_t tiles = (smem_to_u32(smem) + 1023u) & ~1023u;

    const int mode = blockIdx.z, b = blockIdx.y;
    const int tid = threadIdx.x;
    const int wid = tid >> 5, lane = tid & 31;
    const int hA = (mode == 0) ? 3 : 0;   // Qc | Qu (A-split)
    const int hB = (mode == 0) ? 2 : 1;   // Vu | Ku (single)

    // decode both jobs
    int i0a[2], j0a[2];
#pragma unroll
    for (int jj = 0; jj < 2; jj++) {
        int pp = blockIdx.x * 2 + jj;
        int d = 15;
        while (pp >= 16 - d) { pp -= 16 - d; d--; }
        const int rt = (mode == 0) ? (pp + d) : pp;
        const int ct = (mode == 0) ? pp : (pp + d);
        i0a[jj] = rt * 128;
        j0a[jj] = ct * 128;
    }

    const int ltile = tid >> 6;       // 0..3; group 3 idle during loads
    const int llane = tid & 63;
    const int rl = llane >> 3, c16 = llane & 7;

#define PAIR_LOAD(stagebase, i0v, j0v) do { \
    if (ltile < 3) { \
        const __half* src = \
            (ltile == 0) ? g_Ph[hA] + ((size_t)b * SS + (i0v)) * DHE : \
            (ltile == 1) ? g_Pl[hA] + ((size_t)b * SS + (i0v)) * DHE : \
                           g_Ph[hB] + ((size_t)b * SS + (j0v)) * DHE; \
        const __half* g = src + (size_t)rl * DHE + c16 * 8; \
        const uint32_t tsm = (stagebase) + ltile * 16384; \
        _Pragma("unroll") \
        for (int q = 0; q < 16; q++) { \
            const uint32_t so = SW128((uint32_t)((q * 8 + rl) * 128 + c16 * 16)); \
            asm volatile("cp.async.cg.shared.global [%0], [%1], 16;" \
                :: "r"(tsm + so), "l"(g + (size_t)q * 8 * DHE)); \
        } \
    } \
    asm volatile("cp.async.commit_group;"); \
} while (0)

    const int wm = wid >> 1, wn = wid & 1;
    const int lrow = lane & 15;
    const uint32_t kbl = (lane >> 4) * 16;
    const int rr = lane >> 2, cc = (lane & 3) * 2;
    const size_t boff = (size_t)b * SS * SS;

    PAIR_LOAD(tiles, i0a[0], j0a[0]);
    PAIR_LOAD(tiles + 49152, i0a[1], j0a[1]);

    for (int jj = 0; jj < 2; jj++) {
        if (jj == 0) asm volatile("cp.async.wait_group 1;");
        else         asm volatile("cp.async.wait_group 0;");
        __syncthreads();

        const uint32_t stg = tiles + jj * 49152;
        const uint32_t stAh = stg, stAl = stg + 16384, stBf = stg + 32768;
        const int i0 = i0a[jj], j0 = j0a[jj];

        float acc[2][8][4];
#pragma unroll
        for (int mf = 0; mf < 2; mf++)
#pragma unroll
            for (int nf = 0; nf < 8; nf++)
#pragma unroll
                for (int q = 0; q < 4; q++) acc[mf][nf][q] = 0.f;

#pragma unroll
        for (int ks = 0; ks < 4; ks++) {
            const uint32_t kb = ks * 32 + kbl;
            uint32_t ah[2][4], al[2][4], bh[4][4];
#pragma unroll
            for (int mf = 0; mf < 2; mf++) {
                const uint32_t off = SW128((uint32_t)((wm * 32 + mf * 16 + lrow) * 128) + kb);
                ldsm4(ah[mf], stAh + off);
                ldsm4(al[mf], stAl + off);
            }
#pragma unroll
            for (int np = 0; np < 4; np++) {
                const uint32_t off = SW128((uint32_t)((wn * 64 + np * 16 + lrow) * 128) + kb);
                ldsm4(bh[np], stBf + off);
            }
#pragma unroll
            for (int mf = 0; mf < 2; mf++)
#pragma unroll
                for (int nf = 0; nf < 8; nf++) {
                    const int np = nf >> 1, sel = nf & 1;
                    mma16816(acc[mf][nf], ah[mf], bh[np][sel], bh[np][sel + 2]);
                }
#pragma unroll
            for (int mf = 0; mf < 2; mf++)
#pragma unroll
                for (int nf = 0; nf < 8; nf++) {
                    const int np = nf >> 1, sel = nf & 1;
                    mma16816(acc[mf][nf], al[mf], bh[np][sel], bh[np][sel + 2]);
                }
        }

        if (mode == 0) {
            __half* outh = g_t1h + boff;
            __half* outl = g_t1l + boff;
#pragma unroll
            for (int mf = 0; mf < 2; mf++)
#pragma unroll
                for (int half = 0; half < 2; half++) {
                    const int gi = i0 + wm * 32 + mf * 16 + half * 8 + rr;
#pragma unroll
                    for (int nf = 0; nf < 8; nf++) {
                        const int gc = j0 + wn * 64 + nf * 8 + cc;
                        float v0 = acc[mf][nf][half * 2 + 0] * SCALE;
                        float v1 = acc[mf][nf][half * 2 + 1] * SCALE;
                        v0 = (gc <= gi) ? v0 : 0.f;
                        v1 = (gc + 1 <= gi) ? v1 : 0.f;
                        uint32_t h, l;
                        split2h(v0, v1, h, l);
                        *(uint32_t*)(outh + (size_t)gi * SS + gc) = h;
                        *(uint32_t*)(outl + (size_t)gi * SS + gc) = l;
                    }
                }
        } else {
            __half* outh = g_sgh + boff;
#pragma unroll
            for (int mf = 0; mf < 2; mf++)
#pragma unroll
                for (int half = 0; half < 2; half++) {
                    const int gi = i0 + wm * 32 + mf * 16 + half * 8 + rr;
#pragma unroll
                    for (int nf = 0; nf < 8; nf++) {
                        const int gc = j0 + wn * 64 + nf * 8 + cc;
                        float v0 = acc[mf][nf][half * 2 + 0] * SCALE;
                        float v1 = acc[mf][nf][half * 2 + 1] * SCALE;
                        v0 = (gc > gi) ? fast_sigmoid(v0) : 0.f;
                        v1 = (gc + 1 > gi) ? fast_sigmoid(v1) : 0.f;
                        *(uint32_t*)(outh + (size_t)gi * SS + gc) = pack2h(v0, v1);
                    }
                }
        }
    }
#undef PAIR_LOAD
}

// ---------------------------------------------------------------------------
// K3: S_u via mma.sync f16 A-split (2 products), j-SPLIT, 2-stage pipeline.
// grid (272, 1, 4 b), 256 thr, 99328 B smem.  (unchanged from R13)
// ---------------------------------------------------------------------------
__global__ void __launch_bounds__(256) k_su_mma() {
    extern __shared__ char smem[];
    const uint32_t tiles = (smem_to_u32(smem) + 1023u) & ~1023u;

    const int b = blockIdx.z;
    const int seg = blockIdx.x & 1;
    int pp = blockIdx.x >> 1;
    int d = 15;
    while (pp >= 16 - d) { pp -= 16 - d; d--; }
    const int kt = pp, it = pp + d;
    const int i0 = it * 128, k0 = kt * 128;

    int jbeg = k0, jend = (it + 1) * 128;
    const int mid = jbeg + ((jend - jbeg) >> 1);
    if (seg == 0) jend = mid; else jbeg = mid;
    const int nch = (jend - jbeg) >> 6;

    const int tid = threadIdx.x;
    const int wid = tid >> 5, lane = tid & 31;

    const int ltile = tid >> 6;
    const int llane = tid & 63;
    const int rl = llane >> 3;
    const int c16 = llane & 7;
    const size_t boff = (size_t)b * SS * SS;
    const __half* src =
        (ltile == 0) ? g_t1h + boff + (size_t)i0 * SS :
        (ltile == 1) ? g_t1l + boff + (size_t)i0 * SS :
                       g_sgh + boff + (size_t)k0 * SS;
    const __half* gbase = src + (size_t)rl * SS + c16 * 8;
    const uint32_t tsm = tiles + ltile * 16384;

#define SU_LOAD_CHUNK(stage, j0v) do { \
    if (ltile < 3) { \
        const __half* _g = gbase + (j0v); \
        const uint32_t _base = tsm + (stage) * 49152; \
        _Pragma("unroll") \
        for (int q = 0; q < 16; q++) { \
            uint32_t so = (uint32_t)((q * 8 + rl) * 128 + c16 * 16); \
            uint32_t sa = _base + SW128(so); \
            asm volatile("cp.async.cg.shared.global [%0], [%1], 16;" :: "r"(sa), "l"(_g + (size_t)q * 8 * SS)); \
        } \
    } \
    asm volatile("cp.async.commit_group;"); \
} while (0)

    float acc[2][8][4];
#pragma unroll
    for (int mf = 0; mf < 2; mf++)
#pragma unroll
        for (int nf = 0; nf < 8; nf++)
#pragma unroll
            for (int q = 0; q < 4; q++) acc[mf][nf][q] = 0.f;

    const int wm = wid >> 1, wn = wid & 1;
    const int lrow = lane & 15;
    const uint32_t kbl = (lane >> 4) * 16;

    SU_LOAD_CHUNK(0, jbeg);

    for (int i = 0; i < nch; i++) {
        const int s = i & 1;
        if (i + 1 < nch) {
            SU_LOAD_CHUNK(s ^ 1, jbeg + (i + 1) * 64);
            asm volatile("cp.async.wait_group 1;");
        } else {
            asm volatile("cp.async.wait_group 0;");
        }
        __syncthreads();

        const uint32_t stAh = tiles + s * 49152;
        const uint32_t stAl = stAh + 16384;
        const uint32_t stBf = stAh + 32768;

#pragma unroll
        for (int ks = 0; ks < 4; ks++) {
            const uint32_t kb = ks * 32 + kbl;
            uint32_t ah[2][4], al[2][4], bh[4][4];
#pragma unroll
            for (int mf = 0; mf < 2; mf++) {
                const uint32_t off = SW128((uint32_t)((wm * 32 + mf * 16 + lrow) * 128) + kb);
                ldsm4(ah[mf], stAh + off);
                ldsm4(al[mf], stAl + off);
            }
#pragma unroll
            for (int np = 0; np < 4; np++) {
                const uint32_t off = SW128((uint32_t)((wn * 64 + np * 16 + lrow) * 128) + kb);
                ldsm4(bh[np], stBf + off);
            }
#pragma unroll
            for (int mf = 0; mf < 2; mf++)
#pragma unroll
                for (int nf = 0; nf < 8; nf++) {
                    const int np = nf >> 1, sel = nf & 1;
                    mma16816(acc[mf][nf], ah[mf], bh[np][sel], bh[np][sel + 2]);
                }
#pragma unroll
            for (int mf = 0; mf < 2; mf++)
#pragma unroll
                for (int nf = 0; nf < 8; nf++) {
                    const int np = nf >> 1, sel = nf & 1;
                    mma16816(acc[mf][nf], al[mf], bh[np][sel], bh[np][sel + 2]);
                }
        }
        __syncthreads();
    }
#undef SU_LOAD_CHUNK

    float* C = (seg ? g_suB : g_suA) + boff;
    const int rr = lane >> 2, cc = (lane & 3) * 2;
#pragma unroll
    for (int mf = 0; mf < 2; mf++) {
        const int gr = i0 + wm * 32 + mf * 16 + rr;
#pragma unroll
        for (int nf = 0; nf < 8; nf++) {
            const int gc = k0 + wn * 64 + nf * 8 + cc;
            *(float2*)(C + (size_t)gr * SS + gc) = make_float2(acc[mf][nf][0], acc[mf][nf][1]);
            *(float2*)(C + (size_t)(gr + 8) * SS + gc) = make_float2(acc[mf][nf][2], acc[mf][nf][3]);
        }
    }
}

// ---------------------------------------------------------------------------
// K4: flash attention partial via mma.sync f16 (2 products), 2 k-tiles/chunk,
// DOUBLE-BUFFERED K/V (prefetch next k-tile during compute).
// smem: Qh 16K | Ql 16K | K0 16K | V0 16K | K1 16K | V1 16K = 99328 B.
// grid (16 it, 8 chunk, 4 b), 256 thr.
// ---------------------------------------------------------------------------
__global__ void __launch_bounds__(256) k_attn_mma() {
    const int it = blockIdx.x, chunk = blockIdx.y, b = blockIdx.z;
    if (chunk * 2 > it) return;
    const int kt_beg = chunk * 2;
    const int kt_end = min(kt_beg + 2, it + 1);
    const int i0 = it * 128;

    extern __shared__ char smem[];
    const uint32_t sb = (smem_to_u32(smem) + 1023u) & ~1023u;
    const uint32_t smQh = sb;
    const uint32_t smQl = sb + 16384;
    const uint32_t smKV = sb + 32768;   // [stage] K 16K | V 16K, stage stride 32768

    const int tid = threadIdx.x;
    const int wid = tid >> 5, lane = tid & 31;
    const int m0 = wid * 16;
    const int lrow = lane & 15;
    const uint32_t kbl = (lane >> 4) * 16;
    const int rr = lane >> 2, cc = (lane & 3) * 2;

#define ATTN_LOAD_KV(stage, ktv) do { \
    const int _k0 = (ktv) * 128; \
    const uint32_t _sk = smKV + (stage) * 32768; \
    const uint32_t _sv = _sk + 16384; \
    for (int t = tid; t < 1024; t += 256) { \
        const int r = t >> 3, c16 = t & 7; \
        const __half* srcp = g_Ph[4] + ((size_t)b * SS + _k0 + r) * DHE + c16 * 8; \
        asm volatile("cp.async.cg.shared.global [%0], [%1], 16;" \
            :: "r"(_sk + SW128((uint32_t)(r * 128 + c16 * 16))), "l"(srcp)); \
    } \
    for (int t = tid; t < 1024; t += 256) { \
        const int rw = t >> 3, c16 = t & 7; \
        const int dd = rw & 63, sub = rw >> 6; \
        const __half* srcp = g_Vtf + ((size_t)b * DHE + dd) * SS + _k0 + sub * 64 + c16 * 8; \
        const uint32_t dst = _sv + sub * 8192 + SW128((uint32_t)(dd * 128 + c16 * 16)); \
        asm volatile("cp.async.cg.shared.global [%0], [%1], 16;" :: "r"(dst), "l"(srcp)); \
    } \
    asm volatile("cp.async.commit_group;"); \
} while (0)

    // Q once (group 0), then KV for first k-tile (group 1)
    for (int t = tid; t < 2048; t += 256) {
        const int half = t >> 10, r = (t >> 3) & 127, c16 = t & 7;
        const __half* src = (half ? g_Pl[3] : g_Ph[3])
            + ((size_t)b * SS + i0 + r) * DHE + c16 * 8;
        const uint32_t dst = (half ? smQl : smQh) + SW128((uint32_t)(r * 128 + c16 * 16));
        asm volatile("cp.async.cg.shared.global [%0], [%1], 16;" :: "r"(dst), "l"(src));
    }
    asm volatile("cp.async.commit_group;");
    ATTN_LOAD_KV(0, kt_beg);

    const float* SuA = g_suA + (size_t)b * SS * SS;
    const float* SuB = g_suB + (size_t)b * SS * SS;

    float m[2] = {-1e30f, -1e30f}, l[2] = {0.f, 0.f};
    float accO[8][4];
#pragma unroll
    for (int nf = 0; nf < 8; nf++)
#pragma unroll
        for (int q = 0; q < 4; q++) accO[nf][q] = 0.f;

    for (int kt = kt_beg; kt < kt_end; kt++) {
        const int s = (kt - kt_beg) & 1;
        if (kt + 1 < kt_end) {
            ATTN_LOAD_KV(s ^ 1, kt + 1);
            asm volatile("cp.async.wait_group 1;");
        } else {
            asm volatile("cp.async.wait_group 0;");
        }
        __syncthreads();

        const int k0t = kt * 128;
        const uint32_t smK = smKV + s * 32768;
        const uint32_t smV = smK + 16384;

        // ---- Sc = Q K^T (2 products) ----
        float accS[16][4];
#pragma unroll
        for (int nf = 0; nf < 16; nf++)
#pragma unroll
            for (int q = 0; q < 4; q++) accS[nf][q] = 0.f;

#pragma unroll
        for (int ks = 0; ks < 4; ks++) {
            const uint32_t kb = ks * 32 + kbl;
            uint32_t ah[4], al[4];
            const uint32_t aoff = SW128((uint32_t)((m0 + lrow) * 128) + kb);
            ldsm4(ah, smQh + aoff);
            ldsm4(al, smQl + aoff);
#pragma unroll
            for (int g = 0; g < 2; g++) {
                uint32_t bh[4][4];
#pragma unroll
                for (int n4 = 0; n4 < 4; n4++) {
                    const int np = g * 4 + n4;
                    const uint32_t boffs = SW128((uint32_t)((np * 16 + lrow) * 128) + kb);
                    ldsm4(bh[n4], smK + boffs);
                }
#pragma unroll
                for (int n4 = 0; n4 < 4; n4++)
#pragma unroll
                    for (int sel = 0; sel < 2; sel++)
                        mma16816(accS[(g * 4 + n4) * 2 + sel], ah, bh[n4][sel], bh[n4][sel + 2]);
#pragma unroll
                for (int n4 = 0; n4 < 4; n4++)
#pragma unroll
                    for (int sel = 0; sel < 2; sel++)
                        mma16816(accS[(g * 4 + n4) * 2 + sel], al, bh[n4][sel], bh[n4][sel + 2]);
            }
        }

        // ---- logits ----
        const bool diag = (kt == it);
#pragma unroll
        for (int nf = 0; nf < 16; nf++) {
            const int gk = k0t + nf * 8 + cc;
#pragma unroll
            for (int half = 0; half < 2; half++) {
                const int gi = i0 + m0 + half * 8 + rr;
                const float2 a2 = *(const float2*)(SuA + (size_t)gi * SS + gk);
                const float2 b2 = *(const float2*)(SuB + (size_t)gi * SS + gk);
                float v0 = accS[nf][half * 2 + 0] * SCALE - fast_silu(a2.x + b2.x);
                float v1 = accS[nf][half * 2 + 1] * SCALE - fast_silu(a2.y + b2.y);
                if (diag) {
                    if (gk > gi) v0 = -1e30f;
                    if (gk + 1 > gi) v1 = -1e30f;
                }
                accS[nf][half * 2 + 0] = v0;
                accS[nf][half * 2 + 1] = v1;
            }
        }

        // ---- online softmax ----
#pragma unroll
        for (int half = 0; half < 2; half++) {
            float mx = -1e30f;
#pragma unroll
            for (int nf = 0; nf < 16; nf++)
                mx = fmaxf(mx, fmaxf(accS[nf][half * 2], accS[nf][half * 2 + 1]));
            mx = fmaxf(mx, __shfl_xor_sync(0xffffffffu, mx, 1));
            mx = fmaxf(mx, __shfl_xor_sync(0xffffffffu, mx, 2));
            const float mnew = fmaxf(m[half], mx);
            const float corr = __expf(m[half] - mnew);
            m[half] = mnew;
            float ps = 0.f;
#pragma unroll
            for (int nf = 0; nf < 16; nf++) {
                const float p0 = __expf(accS[nf][half * 2] - mnew);
                const float p1 = __expf(accS[nf][half * 2 + 1] - mnew);
                accS[nf][half * 2] = p0;
                accS[nf][half * 2 + 1] = p1;
                ps += p0 + p1;
            }
            ps += __shfl_xor_sync(0xffffffffu, ps, 1);
            ps += __shfl_xor_sync(0xffffffffu, ps, 2);
            l[half] = l[half] * corr + ps;
#pragma unroll
            for (int nf = 0; nf < 8; nf++) {
                accO[nf][half * 2] *= corr;
                accO[nf][half * 2 + 1] *= corr;
            }
        }

        // ---- O += P @ V (P split hi/lo, V single: 2 products) ----
#pragma unroll
        for (int ks2 = 0; ks2 < 8; ks2++) {
            uint32_t pah[4], pal[4];
            split2h(accS[2 * ks2][0], accS[2 * ks2][1], pah[0], pal[0]);
            split2h(accS[2 * ks2][2], accS[2 * ks2][3], pah[1], pal[1]);
            split2h(accS[2 * ks2 + 1][0], accS[2 * ks2 + 1][1], pah[2], pal[2]);
            split2h(accS[2 * ks2 + 1][2], accS[2 * ks2 + 1][3], pah[3], pal[3]);
            const uint32_t sub = (ks2 >> 2) * 8192;
            const uint32_t kb2 = (ks2 & 3) * 32 + kbl;
            uint32_t vh[4][4];
#pragma unroll
            for (int np = 0; np < 4; np++) {
                const uint32_t voff = sub + SW128((uint32_t)((np * 16 + lrow) * 128) + kb2);
                ldsm4(vh[np], smV + voff);
            }
#pragma unroll
            for (int np = 0; np < 4; np++)
#pragma unroll
                for (int sel = 0; sel < 2; sel++)
                    mma16816(accO[np * 2 + sel], pah, vh[np][sel], vh[np][sel + 2]);
#pragma unroll
            for (int np = 0; np < 4; np++)
#pragma unroll
                for (int sel = 0; sel < 2; sel++)
                    mma16816(accO[np * 2 + sel], pal, vh[np][sel], vh[np][sel + 2]);
        }
    }
#undef ATTN_LOAD_KV

    if ((lane & 3) == 0) {
        g_am[b][chunk][it][m0 + rr] = m[0];
        g_am[b][chunk][it][m0 + 8 + rr] = m[1];
        g_al[b][chunk][it][m0 + rr] = l[0];
        g_al[b][chunk][it][m0 + 8 + rr] = l[1];
    }
    float* aO = g_aO[b][chunk][it];
#pragma unroll
    for (int nf = 0; nf < 8; nf++) {
        const int gc = nf * 8 + cc;
        *(float2*)(aO + (m0 + rr) * 64 + gc) = make_float2(accO[nf][0], accO[nf][1]);
        *(float2*)(aO + (m0 + 8 + rr) * 64 + gc) = make_float2(accO[nf][2], accO[nf][3]);
    }
}

// ---------------------------------------------------------------------------
// K5: combine split-KV partials.  grid (16 it, 4 b), 256 thr.
// ---------------------------------------------------------------------------
__global__ void k_comb(float* __restrict__ out) {
    const int it = blockIdx.x, b = blockIdx.y;
    const int nch = it / 2 + 1;
    const int tid = threadIdx.x;
    const int r = tid >> 1;
    const int c0 = (tid & 1) * 32;

    float M = -1e30f;
#pragma unroll
    for (int c = 0; c < 8; c++)
        if (c < nch) M = fmaxf(M, g_am[b][c][it][r]);

    float w[8];
    float lt = 0.f;
#pragma unroll
    for (int c = 0; c < 8; c++) {
        w[c] = 0.f;
        if (c < nch) {
            w[c] = __expf(g_am[b][c][it][r] - M);
            lt += g_al[b][c][it][r] * w[c];
        }
    }
    const float inv = 1.f / lt;

    float* dst = out + ((size_t)b * SS + it * 128 + r) * DHE + c0;
#pragma unroll
    for (int j4 = 0; j4 < 8; j4++) {
        float4 acc = make_float4(0.f, 0.f, 0.f, 0.f);
#pragma unroll
        for (int c = 0; c < 8; c++)
            if (c < nch) {
                float4 v = *(const float4*)&g_aO[b][c][it][r * 64 + c0 + j4 * 4];
                acc.x = fmaf(v.x, w[c], acc.x);
                acc.y = fmaf(v.y, w[c], acc.y);
                acc.z = fmaf(v.z, w[c], acc.z);
                acc.w = fmaf(v.w, w[c], acc.w);
            }
        *(float4*)(dst + j4 * 4) =
            make_float4(acc.x * inv, acc.y * inv, acc.z * inv, acc.w * inv);
    }
}

// ---------------------------------------------------------------------------
extern "C" void kernel_launch(void* const* d_in, const int* in_sizes, int n_in,
                              void* d_out, int out_size) {
    const float* x   = (const float*)d_in[0];
    const float* wqu = (const float*)d_in[1];
    const float* wku = (const float*)d_in[2];
    const float* wvu = (const float*)d_in[3];
    const float* wqc = (const float*)d_in[4];
    const float* wkc = (const float*)d_in[5];
    const float* wvc = (const float*)d_in[6];
    float* out = (float*)d_out;

    k_cvt<<<2048, 256>>>(x, wqu, wku, wvu, wqc, wkc, wvc);

    const int proj_smem = 1024 + 2 * 40960;  // 82944 B
    cudaFuncSetAttribute(k_proj_mma, cudaFuncAttributeMaxDynamicSharedMemorySize, proj_smem);
    k_proj_mma<<<dim3(64, 6), 256, proj_smem>>>();

    const int pair_smem = 1024 + 2 * 49152;  // 99328 B
    cudaFuncSetAttribute(k_pair_mma, cudaFuncAttributeMaxDynamicSharedMemorySize, pair_smem);
    k_pair_mma<<<dim3(68, 4, 2), 256, pair_smem>>>();

    const int su_smem = 1024 + 2 * 49152;  // 99328 B
    cudaFuncSetAttribute(k_su_mma, cudaFuncAttributeMaxDynamicSharedMemorySize, su_smem);
    k_su_mma<<<dim3(272, 1, 4), 256, su_smem>>>();

    const int attn_smem = 1024 + 6 * 16384;  // 99328 B
    cudaFuncSetAttribute(k_attn_mma, cudaFuncAttributeMaxDynamicSharedMemorySize, attn_smem);
    k_attn_mma<<<dim3(16, 8, 4), 256, attn_smem>>>();

    k_comb<<<dim3(16, 4), 256>>>(out);
}